// round 7
// baseline (speedup 1.0000x reference)
#include <cuda_runtime.h>
#include <cuda_fp16.h>
#include <math.h>

#define NITEMS   32768
#define DIM      512
#define KSEL     16
#define LAMBDA   0.5f
#define DECAYF   0.85f
#define NTHREADS 1024
#define MAXB     512
#define RPW      7                      // rows per warp
#define RPB      (32 * RPW)             // 224 rows per block
#define SMEM_DYN (RPB * DIM * 2)        // 229376 B of fp16 rows

// ---------------- device scratch (no allocations allowed) ----------------
__device__ __align__(16) uint4  g_cand[2][MAXB][64];   // per-block candidate vectors (fp16, row layout)
__device__ float                g_candrel[2][MAXB];    // candidate's rel
__device__ float                g_m_part[MAXB];        // online-softmax partial max
__device__ float                g_s_part[MAXB];        // online-softmax partial sum
__device__ unsigned long long   g_best[KSEL + 1];      // per-iteration global argmax slots
__device__ unsigned int         g_bar;                 // monotonic grid barrier

// ---------------- monotonic grid barrier ----------------
__device__ __forceinline__ void grid_sync(int nb) {
    __syncthreads();
    if (threadIdx.x == 0) {
        __threadfence();
        unsigned int ticket = atomicAdd(&g_bar, 1u) + 1u;
        unsigned int target = ((ticket + (unsigned)nb - 1u) / (unsigned)nb) * (unsigned)nb;
        while (*((volatile unsigned int*)&g_bar) < target) { __nanosleep(32); }
        __threadfence();
    }
    __syncthreads();
}

// order-preserving float->u32; low 32 bits = ~row so ties pick the SMALLEST row
__device__ __forceinline__ unsigned long long pack_si(float s, int row) {
    unsigned int b = __float_as_uint(s);
    unsigned int e = (b & 0x80000000u) ? ~b : (b | 0x80000000u);
    return ((unsigned long long)e << 32) | (unsigned int)(~row);
}

__device__ __forceinline__ float warp_sum_xor(float v) {
    #pragma unroll
    for (int o = 16; o > 0; o >>= 1) v += __shfl_xor_sync(0xffffffffu, v, o);
    return v;
}
__device__ __forceinline__ unsigned long long warp_max_u64(unsigned long long v) {
    #pragma unroll
    for (int o = 16; o > 0; o >>= 1) {
        unsigned long long u = __shfl_down_sync(0xffffffffu, v, o);
        if (u > v) v = u;
    }
    return v;
}
// online-softmax pair merge
__device__ __forceinline__ void merge_ms(float& m, float& s, float m2, float s2) {
    float M = fmaxf(m, m2);
    s = s * expf(m - M) + s2 * expf(m2 - M);
    m = M;
}

__global__ void __launch_bounds__(NTHREADS, 1)
ranking_kernel(const float* __restrict__ pred,
               const float* __restrict__ E,
               float* __restrict__ out,
               int nb)
{
    extern __shared__ __align__(16) __half sm_rows[];   // RPB rows x 512 fp16

    __shared__ unsigned long long sh_u64[32];
    __shared__ float              sh_m[32], sh_s[32];
    __shared__ float              sh_bm, sh_bs;
    __shared__ float              sm_rel[RPB];

    const int tid   = threadIdx.x;
    const int bid   = blockIdx.x;
    const int lid   = tid & 31;
    const int wid   = tid >> 5;
    const int rbase = bid * RPB + wid * RPW;           // first global row of this warp
    const int gthreads = nb * NTHREADS;
    const int gtid     = bid * NTHREADS + tid;

    // reset per-iteration argmax slots (needed on every graph replay); ordered
    // before any atomicMax by the two grid_syncs that precede the first publish
    if (bid == 0 && tid == 0) {
        #pragma unroll
        for (int i = 0; i <= KSEL; i++) g_best[i] = 0ull;
    }

    // ---------------- A1: online softmax over predictions ----------------
    float m = -1e30f, s = 0.f;
    for (int i = gtid; i < NITEMS; i += gthreads) {
        float p = pred[i];
        float M = fmaxf(m, p);
        s = s * expf(m - M) + expf(p - M);
        m = M;
    }
    #pragma unroll
    for (int o = 16; o > 0; o >>= 1) {
        float m2 = __shfl_xor_sync(0xffffffffu, m, o);
        float s2 = __shfl_xor_sync(0xffffffffu, s, o);
        merge_ms(m, s, m2, s2);
    }
    __syncthreads();
    if (lid == 0) { sh_m[wid] = m; sh_s[wid] = s; }
    __syncthreads();
    if (tid < 32) {
        m = sh_m[tid]; s = sh_s[tid];
        #pragma unroll
        for (int o = 16; o > 0; o >>= 1) {
            float m2 = __shfl_xor_sync(0xffffffffu, m, o);
            float s2 = __shfl_xor_sync(0xffffffffu, s, o);
            merge_ms(m, s, m2, s2);
        }
        if (tid == 0) { g_m_part[bid] = m; g_s_part[bid] = s; }
    }
    grid_sync(nb);

    {
        float pm = (tid < nb) ? __ldcg(&g_m_part[tid]) : -1e30f;
        float psv = (tid < nb) ? __ldcg(&g_s_part[tid]) : 0.f;
        #pragma unroll
        for (int o = 16; o > 0; o >>= 1) {
            float m2 = __shfl_xor_sync(0xffffffffu, pm, o);
            float s2 = __shfl_xor_sync(0xffffffffu, psv, o);
            merge_ms(pm, psv, m2, s2);
        }
        __syncthreads();
        if (lid == 0) { sh_m[wid] = pm; sh_s[wid] = psv; }
        __syncthreads();
        if (tid == 0) {
            float mm = sh_m[0], ss = sh_s[0];
            #pragma unroll
            for (int w2 = 1; w2 < 32; w2++) merge_ms(mm, ss, sh_m[w2], sh_s[w2]);
            sh_bm = mm; sh_bs = ss;
        }
        __syncthreads();
    }
    const float pmax = sh_bm;
    const float invS = 1.0f / sh_bs;

    // lane l owns row rbase+l forever; rel & max_sim live in registers
    const bool  mine  = (lid < RPW) && (rbase + lid < NITEMS);
    const int   myrow = rbase + lid;
    float myrel = 0.f, myms = 0.f;
    if (mine) {
        myrel = expf(pred[myrow] - pmax) * invS;
        sm_rel[wid * RPW + lid] = myrel;               // block-local rel table
    }

    // ---------------- A2: normalize -> fp16 into SMEM only ----------------
    {
        const float4* Erow = reinterpret_cast<const float4*>(E) + (size_t)rbase * (DIM / 4);
        float4 cur[4];
        if (rbase < NITEMS) {
            #pragma unroll
            for (int j = 0; j < 4; j++) cur[j] = Erow[j * 32 + lid];
        }
        #pragma unroll
        for (int i = 0; i < RPW; i++) {
            int row = rbase + i;
            float4 nxt[4];
            bool have_n = (i + 1 < RPW) && (row + 1 < NITEMS);
            if (have_n) {
                const float4* Er2 = Erow + (size_t)(i + 1) * (DIM / 4);
                #pragma unroll
                for (int j = 0; j < 4; j++) nxt[j] = Er2[j * 32 + lid];
            }
            if (row < NITEMS) {
                float ss2 = 0.f;
                #pragma unroll
                for (int j = 0; j < 4; j++)
                    ss2 += cur[j].x * cur[j].x + cur[j].y * cur[j].y
                         + cur[j].z * cur[j].z + cur[j].w * cur[j].w;
                ss2 = warp_sum_xor(ss2);
                const float inv = 1.0f / (sqrtf(ss2) + 1e-12f);
                uint2* Es = reinterpret_cast<uint2*>(sm_rows) + (size_t)(wid * RPW + i) * (DIM / 4);
                #pragma unroll
                for (int j = 0; j < 4; j++) {
                    __half2 h0 = __floats2half2_rn(cur[j].x * inv, cur[j].y * inv);
                    __half2 h1 = __floats2half2_rn(cur[j].z * inv, cur[j].w * inv);
                    uint2 u;
                    u.x = *reinterpret_cast<unsigned*>(&h0);
                    u.y = *reinterpret_cast<unsigned*>(&h1);
                    Es[j * 32 + lid] = u;
                }
            }
            #pragma unroll
            for (int j = 0; j < 4; j++) cur[j] = nxt[j];
        }
    }

    // ---------- block best for t=0 (score = rel) + publish candidate ----------
    {
        unsigned long long best = mine ? pack_si(myrel, myrow) : 0ull;
        unsigned long long wmax = warp_max_u64(best);
        if (lid == 0) sh_u64[wid] = wmax;
        __syncthreads();                                // also fences sm_rows for warp0 reads
        if (wid == 0) {
            unsigned long long bb = warp_max_u64(sh_u64[lid]);
            bb = __shfl_sync(0xffffffffu, bb, 0);
            if (bb != 0ull) {
                int r  = (int)(~(unsigned int)bb);
                int lr = r - bid * RPB;
                const uint4* S4 = reinterpret_cast<const uint4*>(sm_rows);
                uint4 c0 = S4[lr * 64 + lid];
                uint4 c1 = S4[lr * 64 + 32 + lid];
                g_cand[0][bid][lid]      = c0;
                g_cand[0][bid][32 + lid] = c1;
                if (lid == 0) g_candrel[0][bid] = sm_rel[lr];
            }
            if (lid == 0) atomicMax(&g_best[0], bb);    // ordered before g_bar by grid_sync's fence
        }
    }
    grid_sync(nb);

    // ---------------- greedy loop ----------------
    float decay_t = 1.0f, err_acc = 0.f, mmr_acc = 0.f;
    for (int t = 0; t < KSEL; t++) {
        // every thread reads the single winner slot (L2 broadcast)
        unsigned long long w = __ldcg(&g_best[t]);
        const int idx = (int)(~(unsigned int)w);
        const int wbk = idx / RPB;

        float candrel = 0.f;
        if (bid == 0 && tid == 0) candrel = __ldcg(&g_candrel[t & 1][wbk]);

        if (t < KSEL - 1) {
            // winner vector from candidate buffer (hot L2), row element layout
            const uint4* Vh = g_cand[t & 1][wbk];
            uint4 v0 = __ldcg(Vh + lid);
            uint4 v1 = __ldcg(Vh + 32 + lid);
            __half2 vh[8];
            {
                const __half2* p0 = reinterpret_cast<const __half2*>(&v0);
                const __half2* p1 = reinterpret_cast<const __half2*>(&v1);
                #pragma unroll
                for (int q = 0; q < 4; q++) { vh[q] = p0[q]; vh[4 + q] = p1[q]; }
            }

            // block0 warp0: accumulate mmr diagonal term = selfdot(winner)
            if (bid == 0 && wid == 0) {
                float sd = 0.f;
                #pragma unroll
                for (int q = 0; q < 8; q++) {
                    float2 f2 = __half22float2(vh[q]);
                    sd = fmaf(f2.x, f2.x, sd);
                    sd = fmaf(f2.y, f2.y, sd);
                }
                sd = warp_sum_xor(sd);
                mmr_acc += sd;
            }

            // 7-row smem GEMV (HFMA2, fp32 cross-chain)
            const uint4* S4 = reinterpret_cast<const uint4*>(sm_rows);
            float f[RPW];
            #pragma unroll
            for (int i = 0; i < RPW; i++) {
                const int lr = wid * RPW + i;
                uint4 a0 = S4[lr * 64 + lid];
                uint4 a1 = S4[lr * 64 + 32 + lid];
                const __half2* h0 = reinterpret_cast<const __half2*>(&a0);
                const __half2* h1 = reinterpret_cast<const __half2*>(&a1);
                __half2 acc_a = __hmul2(h0[0], vh[0]);
                __half2 acc_b = __hmul2(h0[1], vh[1]);
                acc_a = __hfma2(h0[2], vh[2], acc_a);
                acc_b = __hfma2(h0[3], vh[3], acc_b);
                acc_a = __hfma2(h1[0], vh[4], acc_a);
                acc_b = __hfma2(h1[1], vh[5], acc_b);
                acc_a = __hfma2(h1[2], vh[6], acc_a);
                acc_b = __hfma2(h1[3], vh[7], acc_b);
                float2 fa = __half22float2(acc_a);
                float2 fb = __half22float2(acc_b);
                f[i] = (fa.x + fa.y) + (fb.x + fb.y);
            }
            #pragma unroll
            for (int o = 16; o > 0; o >>= 1) {
                #pragma unroll
                for (int i = 0; i < RPW; i++) f[i] += __shfl_xor_sync(0xffffffffu, f[i], o);
            }
            float mysim = 0.f;
            #pragma unroll
            for (int i = 0; i < RPW; i++) if (lid == i) mysim = f[i];

            unsigned long long best = 0ull;
            const float decay_next = decay_t * DECAYF;
            if (mine) {
                myms = (myrow == idx) ? 1e30f : fmaxf(myms, mysim);
                float score = decay_next * myrel - LAMBDA * myms;
                best = pack_si(score, myrow);
            }

            // block reduce + publish candidate for iteration t+1
            unsigned long long wmax = warp_max_u64(best);
            if (lid == 0) sh_u64[wid] = wmax;
            __syncthreads();
            if (wid == 0) {
                unsigned long long bb = warp_max_u64(sh_u64[lid]);
                bb = __shfl_sync(0xffffffffu, bb, 0);
                const int buf = (t + 1) & 1;
                if (bb != 0ull) {
                    int r  = (int)(~(unsigned int)bb);
                    int lr = r - bid * RPB;
                    uint4 c0 = S4[lr * 64 + lid];
                    uint4 c1 = S4[lr * 64 + 32 + lid];
                    g_cand[buf][bid][lid]      = c0;
                    g_cand[buf][bid][32 + lid] = c1;
                    if (lid == 0) g_candrel[buf][bid] = sm_rel[lr];
                }
                if (lid == 0) atomicMax(&g_best[t + 1], bb);
            }
            grid_sync(nb);
        } else {
            // last winner: block0 warp0 adds its selfdot
            if (bid == 0 && wid == 0) {
                const uint4* Vh = g_cand[t & 1][wbk];
                uint4 v0 = __ldcg(Vh + lid);
                uint4 v1 = __ldcg(Vh + 32 + lid);
                const __half2* p0 = reinterpret_cast<const __half2*>(&v0);
                const __half2* p1 = reinterpret_cast<const __half2*>(&v1);
                float sd = 0.f;
                #pragma unroll
                for (int q = 0; q < 4; q++) {
                    float2 a = __half22float2(p0[q]);
                    float2 b = __half22float2(p1[q]);
                    sd = fmaf(a.x, a.x, sd); sd = fmaf(a.y, a.y, sd);
                    sd = fmaf(b.x, b.x, sd); sd = fmaf(b.y, b.y, sd);
                }
                sd = warp_sum_xor(sd);
                mmr_acc += sd;
            }
        }

        if (bid == 0 && tid == 0) err_acc += candrel * decay_t;
        decay_t *= DECAYF;
    }

    if (bid == 0 && tid == 0)
        out[0] = -err_acc - LAMBDA * mmr_acc;
}

extern "C" void kernel_launch(void* const* d_in, const int* in_sizes, int n_in,
                              void* d_out, int out_size) {
    (void)in_sizes; (void)n_in; (void)out_size;
    const float* pred = (const float*)d_in[0];
    const float* E    = (const float*)d_in[5];   // explanation_embeddings [32768, 512]
    float* out        = (float*)d_out;

    int dev = 0;
    cudaGetDevice(&dev);
    int nsm = 0;
    cudaDeviceGetAttribute(&nsm, cudaDevAttrMultiProcessorCount, dev);
    if (nsm <= 0) nsm = 148;
    if (nsm > MAXB) nsm = MAXB;

    cudaFuncSetAttribute(ranking_kernel,
                         cudaFuncAttributeMaxDynamicSharedMemorySize, SMEM_DYN);
    ranking_kernel<<<nsm, NTHREADS, SMEM_DYN>>>(pred, E, out, nsm);
}

// round 8
// speedup vs baseline: 1.2392x; 1.2392x over previous
#include <cuda_runtime.h>
#include <cuda_fp16.h>
#include <math.h>

#define NITEMS   32768
#define DIM      512
#define KSEL     16
#define LAMBDA   0.5f
#define DECAYF   0.85f
#define NTHREADS 1024
#define MAXB     512
#define RPW      7                      // rows per warp
#define RPB      (32 * RPW)             // 224 rows per block
#define SMEM_DYN (RPB * DIM * 2)        // 229376 B of fp16 rows

// ---------------- device scratch (no allocations allowed) ----------------
__device__ __align__(16) uint4  g_cand[2][MAXB][64];   // per-block candidate vectors (fp16, row layout)
__device__ float                g_candrel[2][MAXB];    // candidate's rel
__device__ float                g_m_part[MAXB];        // online-softmax partial max
__device__ float                g_s_part[MAXB];        // online-softmax partial sum
__device__ unsigned long long   g_best[KSEL + 1];      // per-iteration global argmax slots
__device__ unsigned int         g_bar;                 // monotonic grid barrier

// ---------------- monotonic grid barrier (tight spin, t0-only fence) ----------------
__device__ __forceinline__ void grid_sync(int nb) {
    __syncthreads();
    if (threadIdx.x == 0) {
        __threadfence();
        unsigned int ticket = atomicAdd(&g_bar, 1u) + 1u;
        unsigned int target = ((ticket + (unsigned)nb - 1u) / (unsigned)nb) * (unsigned)nb;
        while (*((volatile unsigned int*)&g_bar) < target) { }
        __threadfence();
    }
    __syncthreads();
}

// order-preserving float->u32; low 32 bits = ~row so ties pick the SMALLEST row
__device__ __forceinline__ unsigned long long pack_si(float s, int row) {
    unsigned int b = __float_as_uint(s);
    unsigned int e = (b & 0x80000000u) ? ~b : (b | 0x80000000u);
    return ((unsigned long long)e << 32) | (unsigned int)(~row);
}

__device__ __forceinline__ float warp_sum_xor(float v) {
    #pragma unroll
    for (int o = 16; o > 0; o >>= 1) v += __shfl_xor_sync(0xffffffffu, v, o);
    return v;
}
__device__ __forceinline__ unsigned long long warp_max_u64(unsigned long long v) {
    #pragma unroll
    for (int o = 16; o > 0; o >>= 1) {
        unsigned long long u = __shfl_down_sync(0xffffffffu, v, o);
        if (u > v) v = u;
    }
    return v;
}
// online-softmax pair merge
__device__ __forceinline__ void merge_ms(float& m, float& s, float m2, float s2) {
    float M = fmaxf(m, m2);
    s = s * expf(m - M) + s2 * expf(m2 - M);
    m = M;
}

__global__ void __launch_bounds__(NTHREADS, 1)
ranking_kernel(const float* __restrict__ pred,
               const float* __restrict__ E,
               float* __restrict__ out,
               int nb)
{
    extern __shared__ __align__(16) __half sm_rows[];   // RPB rows x 512 fp16

    // v-buffer (greedy loop) overlaid on softmax scratch (prologue only)
    __shared__ __align__(16) union {
        struct { float m[32]; float s[32]; } soft;
        uint4 v4[64];                                   // winner vector, 1 KB
    } ovl;
    __shared__ unsigned long long sh_u64[32];
    __shared__ unsigned long long sh_w;
    __shared__ float              sh_bm, sh_bs;
    __shared__ float              sm_rel[RPB];

    const int tid   = threadIdx.x;
    const int bid   = blockIdx.x;
    const int lid   = tid & 31;
    const int wid   = tid >> 5;
    const int rbase = bid * RPB + wid * RPW;           // first global row of this warp
    const int gthreads = nb * NTHREADS;
    const int gtid     = bid * NTHREADS + tid;

    // reset per-iteration argmax slots (graph-replay safe); ordered before first
    // publish by the two grid_syncs below
    if (bid == 0 && tid == 0) {
        #pragma unroll
        for (int i = 0; i <= KSEL; i++) g_best[i] = 0ull;
    }

    // ---------------- A1: online softmax over predictions ----------------
    float m = -1e30f, s = 0.f;
    for (int i = gtid; i < NITEMS; i += gthreads) {
        float p = pred[i];
        float M = fmaxf(m, p);
        s = s * expf(m - M) + expf(p - M);
        m = M;
    }
    #pragma unroll
    for (int o = 16; o > 0; o >>= 1) {
        float m2 = __shfl_xor_sync(0xffffffffu, m, o);
        float s2 = __shfl_xor_sync(0xffffffffu, s, o);
        merge_ms(m, s, m2, s2);
    }
    __syncthreads();
    if (lid == 0) { ovl.soft.m[wid] = m; ovl.soft.s[wid] = s; }
    __syncthreads();
    if (tid < 32) {
        m = ovl.soft.m[tid]; s = ovl.soft.s[tid];
        #pragma unroll
        for (int o = 16; o > 0; o >>= 1) {
            float m2 = __shfl_xor_sync(0xffffffffu, m, o);
            float s2 = __shfl_xor_sync(0xffffffffu, s, o);
            merge_ms(m, s, m2, s2);
        }
        if (tid == 0) { g_m_part[bid] = m; g_s_part[bid] = s; }
    }
    grid_sync(nb);

    {
        float pm = (tid < nb) ? __ldcg(&g_m_part[tid]) : -1e30f;
        float psv = (tid < nb) ? __ldcg(&g_s_part[tid]) : 0.f;
        #pragma unroll
        for (int o = 16; o > 0; o >>= 1) {
            float m2 = __shfl_xor_sync(0xffffffffu, pm, o);
            float s2 = __shfl_xor_sync(0xffffffffu, psv, o);
            merge_ms(pm, psv, m2, s2);
        }
        __syncthreads();
        if (lid == 0) { ovl.soft.m[wid] = pm; ovl.soft.s[wid] = psv; }
        __syncthreads();
        if (tid == 0) {
            float mm = ovl.soft.m[0], ss = ovl.soft.s[0];
            #pragma unroll
            for (int w2 = 1; w2 < 32; w2++) merge_ms(mm, ss, ovl.soft.m[w2], ovl.soft.s[w2]);
            sh_bm = mm; sh_bs = ss;
        }
        __syncthreads();
    }
    const float pmax = sh_bm;
    const float invS = 1.0f / sh_bs;

    // lane l owns row rbase+l forever; rel & max_sim live in registers
    const bool  mine  = (lid < RPW) && (rbase + lid < NITEMS);
    const int   myrow = rbase + lid;
    float myrel = 0.f, myms = 0.f;
    if (mine) {
        myrel = expf(pred[myrow] - pmax) * invS;
        sm_rel[wid * RPW + lid] = myrel;               // block-local rel table
    }

    // ---------------- A2: normalize -> fp16 into SMEM only ----------------
    {
        const float4* Erow = reinterpret_cast<const float4*>(E) + (size_t)rbase * (DIM / 4);
        float4 cur[4];
        if (rbase < NITEMS) {
            #pragma unroll
            for (int j = 0; j < 4; j++) cur[j] = Erow[j * 32 + lid];
        }
        #pragma unroll
        for (int i = 0; i < RPW; i++) {
            int row = rbase + i;
            float4 nxt[4];
            bool have_n = (i + 1 < RPW) && (row + 1 < NITEMS);
            if (have_n) {
                const float4* Er2 = Erow + (size_t)(i + 1) * (DIM / 4);
                #pragma unroll
                for (int j = 0; j < 4; j++) nxt[j] = Er2[j * 32 + lid];
            }
            if (row < NITEMS) {
                float ss2 = 0.f;
                #pragma unroll
                for (int j = 0; j < 4; j++)
                    ss2 += cur[j].x * cur[j].x + cur[j].y * cur[j].y
                         + cur[j].z * cur[j].z + cur[j].w * cur[j].w;
                ss2 = warp_sum_xor(ss2);
                const float inv = 1.0f / (sqrtf(ss2) + 1e-12f);
                uint2* Es = reinterpret_cast<uint2*>(sm_rows) + (size_t)(wid * RPW + i) * (DIM / 4);
                #pragma unroll
                for (int j = 0; j < 4; j++) {
                    __half2 h0 = __floats2half2_rn(cur[j].x * inv, cur[j].y * inv);
                    __half2 h1 = __floats2half2_rn(cur[j].z * inv, cur[j].w * inv);
                    uint2 u;
                    u.x = *reinterpret_cast<unsigned*>(&h0);
                    u.y = *reinterpret_cast<unsigned*>(&h1);
                    Es[j * 32 + lid] = u;
                }
            }
            #pragma unroll
            for (int j = 0; j < 4; j++) cur[j] = nxt[j];
        }
    }

    // ---------- block best for t=0 (score = rel) + publish candidate ----------
    {
        unsigned long long best = mine ? pack_si(myrel, myrow) : 0ull;
        unsigned long long wmax = warp_max_u64(best);
        if (lid == 0) sh_u64[wid] = wmax;
        __syncthreads();                                // also fences sm_rows for warp0 reads
        if (wid == 0) {
            unsigned long long bb = warp_max_u64(sh_u64[lid]);
            bb = __shfl_sync(0xffffffffu, bb, 0);
            if (bb != 0ull) {
                int r  = (int)(~(unsigned int)bb);
                int lr = r - bid * RPB;
                const uint4* S4 = reinterpret_cast<const uint4*>(sm_rows);
                uint4 c0 = S4[lr * 64 + lid];
                uint4 c1 = S4[lr * 64 + 32 + lid];
                g_cand[0][bid][lid]      = c0;
                g_cand[0][bid][32 + lid] = c1;
                if (lid == 0) g_candrel[0][bid] = sm_rel[lr];
            }
            if (lid == 0) atomicMax(&g_best[0], bb);    // ordered before g_bar by grid_sync's fence
        }
    }
    grid_sync(nb);

    // ---------------- greedy loop ----------------
    float decay_t = 1.0f, err_acc = 0.f, mmr_acc = 0.f;
    for (int t = 0; t < KSEL; t++) {
        // warp 0 only: read winner slot (1 L2 read/block) and stage winner vector to smem
        if (wid == 0) {
            unsigned long long w = 0ull;
            if (lid == 0) w = __ldcg(&g_best[t]);
            w = __shfl_sync(0xffffffffu, w, 0);
            const int idx0 = (int)(~(unsigned int)w);
            const int wbk0 = idx0 / RPB;
            if (t < KSEL - 1 || bid == 0) {
                const uint4* Vh = g_cand[t & 1][wbk0];
                ovl.v4[lid]      = __ldcg(Vh + lid);
                ovl.v4[32 + lid] = __ldcg(Vh + 32 + lid);
            }
            if (lid == 0) sh_w = w;
        }
        __syncthreads();

        const unsigned long long w = sh_w;
        const int idx = (int)(~(unsigned int)w);
        const int wbk = idx / RPB;

        if (bid == 0 && tid == 0) err_acc += __ldcg(&g_candrel[t & 1][wbk]) * decay_t;

        // block0 warp0: mmr diagonal term = selfdot(winner), every iteration
        if (bid == 0 && wid == 0) {
            uint4 v0 = ovl.v4[lid];
            uint4 v1 = ovl.v4[32 + lid];
            const __half2* p0 = reinterpret_cast<const __half2*>(&v0);
            const __half2* p1 = reinterpret_cast<const __half2*>(&v1);
            float sd = 0.f;
            #pragma unroll
            for (int q = 0; q < 4; q++) {
                float2 a = __half22float2(p0[q]);
                float2 b = __half22float2(p1[q]);
                sd = fmaf(a.x, a.x, sd); sd = fmaf(a.y, a.y, sd);
                sd = fmaf(b.x, b.x, sd); sd = fmaf(b.y, b.y, sd);
            }
            sd = warp_sum_xor(sd);
            mmr_acc += sd;
        }

        if (t < KSEL - 1) {
            // winner vector from smem staging buffer (conflict-free LDS)
            uint4 v0 = ovl.v4[lid];
            uint4 v1 = ovl.v4[32 + lid];
            __half2 vh[8];
            {
                const __half2* p0 = reinterpret_cast<const __half2*>(&v0);
                const __half2* p1 = reinterpret_cast<const __half2*>(&v1);
                #pragma unroll
                for (int q = 0; q < 4; q++) { vh[q] = p0[q]; vh[4 + q] = p1[q]; }
            }

            // 7-row smem GEMV (HFMA2, fp32 cross-chain)
            const uint4* S4 = reinterpret_cast<const uint4*>(sm_rows);
            float f[RPW];
            #pragma unroll
            for (int i = 0; i < RPW; i++) {
                const int lr = wid * RPW + i;
                uint4 a0 = S4[lr * 64 + lid];
                uint4 a1 = S4[lr * 64 + 32 + lid];
                const __half2* h0 = reinterpret_cast<const __half2*>(&a0);
                const __half2* h1 = reinterpret_cast<const __half2*>(&a1);
                __half2 acc_a = __hmul2(h0[0], vh[0]);
                __half2 acc_b = __hmul2(h0[1], vh[1]);
                acc_a = __hfma2(h0[2], vh[2], acc_a);
                acc_b = __hfma2(h0[3], vh[3], acc_b);
                acc_a = __hfma2(h1[0], vh[4], acc_a);
                acc_b = __hfma2(h1[1], vh[5], acc_b);
                acc_a = __hfma2(h1[2], vh[6], acc_a);
                acc_b = __hfma2(h1[3], vh[7], acc_b);
                float2 fa = __half22float2(acc_a);
                float2 fb = __half22float2(acc_b);
                f[i] = (fa.x + fa.y) + (fb.x + fb.y);
            }
            #pragma unroll
            for (int o = 16; o > 0; o >>= 1) {
                #pragma unroll
                for (int i = 0; i < RPW; i++) f[i] += __shfl_xor_sync(0xffffffffu, f[i], o);
            }
            float mysim = 0.f;
            #pragma unroll
            for (int i = 0; i < RPW; i++) if (lid == i) mysim = f[i];

            unsigned long long best = 0ull;
            const float decay_next = decay_t * DECAYF;
            if (mine) {
                myms = (myrow == idx) ? 1e30f : fmaxf(myms, mysim);
                float score = decay_next * myrel - LAMBDA * myms;
                best = pack_si(score, myrow);
            }

            // block reduce + publish candidate for iteration t+1
            unsigned long long wmax = warp_max_u64(best);
            if (lid == 0) sh_u64[wid] = wmax;
            __syncthreads();
            if (wid == 0) {
                unsigned long long bb = warp_max_u64(sh_u64[lid]);
                bb = __shfl_sync(0xffffffffu, bb, 0);
                const int buf = (t + 1) & 1;
                if (bb != 0ull) {
                    int r  = (int)(~(unsigned int)bb);
                    int lr = r - bid * RPB;
                    uint4 c0 = S4[lr * 64 + lid];
                    uint4 c1 = S4[lr * 64 + 32 + lid];
                    g_cand[buf][bid][lid]      = c0;
                    g_cand[buf][bid][32 + lid] = c1;
                    if (lid == 0) g_candrel[buf][bid] = sm_rel[lr];
                }
                if (lid == 0) atomicMax(&g_best[t + 1], bb);
            }
            grid_sync(nb);
        }

        decay_t *= DECAYF;
    }

    if (bid == 0 && tid == 0)
        out[0] = -err_acc - LAMBDA * mmr_acc;
}

extern "C" void kernel_launch(void* const* d_in, const int* in_sizes, int n_in,
                              void* d_out, int out_size) {
    (void)in_sizes; (void)n_in; (void)out_size;
    const float* pred = (const float*)d_in[0];
    const float* E    = (const float*)d_in[5];   // explanation_embeddings [32768, 512]
    float* out        = (float*)d_out;

    int dev = 0;
    cudaGetDevice(&dev);
    int nsm = 0;
    cudaDeviceGetAttribute(&nsm, cudaDevAttrMultiProcessorCount, dev);
    if (nsm <= 0) nsm = 148;
    if (nsm > MAXB) nsm = MAXB;

    cudaFuncSetAttribute(ranking_kernel,
                         cudaFuncAttributeMaxDynamicSharedMemorySize, SMEM_DYN);
    ranking_kernel<<<nsm, NTHREADS, SMEM_DYN>>>(pred, E, out, nsm);
}

// round 10
// speedup vs baseline: 1.3292x; 1.0726x over previous
#include <cuda_runtime.h>
#include <cuda_fp16.h>
#include <math.h>

#define NITEMS   32768
#define DIM      512
#define KSEL     16
#define LAMBDA   0.5f
#define DECAYF   0.85f
#define NTHREADS 1024
#define MAXB     512
#define RPW      7                      // rows per warp
#define RPB      (32 * RPW)             // 224 rows per block
#define SMEM_DYN (RPB * DIM * 2)        // 229376 B of fp16 rows

// ---------------- device scratch (no allocations allowed) ----------------
__device__ __align__(16) uint4  g_cand[2][MAXB][64];   // per-block candidate vectors (fp16)
__device__ float                g_candrel[2][MAXB];    // candidate's rel
__device__ float                g_m_part[MAXB];        // online-softmax partial max
__device__ float                g_s_part[MAXB];        // online-softmax partial sum
__device__ unsigned long long   g_best[KSEL + 1];      // per-iteration global argmax slots
__device__ unsigned int         g_bar;                 // monotonic grid barrier

// ---------------- monotonic grid barrier (prologue helper) ----------------
__device__ __forceinline__ void grid_sync(int nb) {
    __syncthreads();
    if (threadIdx.x == 0) {
        __threadfence();
        unsigned int ticket = atomicAdd(&g_bar, 1u) + 1u;
        unsigned int target = ((ticket + (unsigned)nb - 1u) / (unsigned)nb) * (unsigned)nb;
        while (*((volatile unsigned int*)&g_bar) < target) { }
        __threadfence();
    }
    __syncthreads();
}

// order-preserving float->u32 (monotone increasing); 0 is reserved for "invalid"
__device__ __forceinline__ unsigned flip_f(float s) {
    unsigned b = __float_as_uint(s);
    return (b & 0x80000000u) ? ~b : (b | 0x80000000u);
}

__device__ __forceinline__ float warp_sum_xor(float v) {
    #pragma unroll
    for (int o = 16; o > 0; o >>= 1) v += __shfl_xor_sync(0xffffffffu, v, o);
    return v;
}
// online-softmax pair merge
__device__ __forceinline__ void merge_ms(float& m, float& s, float m2, float s2) {
    float M = fmaxf(m, m2);
    s = s * expf(m - M) + s2 * expf(m2 - M);
    m = M;
}

__global__ void __launch_bounds__(NTHREADS, 1)
ranking_kernel(const float* __restrict__ pred,
               const float* __restrict__ E,
               float* __restrict__ out,
               int nb)
{
    extern __shared__ __align__(16) __half sm_rows[];   // RPB rows x 512 fp16

    __shared__ __align__(16) union {
        struct { float m[32]; float s[32]; } soft;      // prologue only
        uint4 v4[64];                                   // winner vector, 1 KB
    } ovl;
    __shared__ unsigned sh_e[32];
    __shared__ int      sh_r[32];
    __shared__ int      sh_widx;                        // staged winner row
    __shared__ float    sh_bm, sh_bs;
    __shared__ float    sm_rel[RPB];

    const int tid   = threadIdx.x;
    const int bid   = blockIdx.x;
    const int lid   = tid & 31;
    const int wid   = tid >> 5;
    const int rbase = bid * RPB + wid * RPW;
    const int gthreads = nb * NTHREADS;
    const int gtid     = bid * NTHREADS + tid;
    const uint4* S4 = reinterpret_cast<const uint4*>(sm_rows);

    // reset per-iteration argmax slots (graph-replay safe); published by grid_sync #1
    if (bid == 0 && tid == 0) {
        #pragma unroll
        for (int i = 0; i <= KSEL; i++) g_best[i] = 0ull;
    }

    // ---------------- A1: online softmax over predictions ----------------
    float m = -1e30f, s = 0.f;
    for (int i = gtid; i < NITEMS; i += gthreads) {
        float p = pred[i];
        float M = fmaxf(m, p);
        s = s * expf(m - M) + expf(p - M);
        m = M;
    }
    #pragma unroll
    for (int o = 16; o > 0; o >>= 1) {
        float m2 = __shfl_xor_sync(0xffffffffu, m, o);
        float s2 = __shfl_xor_sync(0xffffffffu, s, o);
        merge_ms(m, s, m2, s2);
    }
    __syncthreads();
    if (lid == 0) { ovl.soft.m[wid] = m; ovl.soft.s[wid] = s; }
    __syncthreads();
    if (tid < 32) {
        m = ovl.soft.m[tid]; s = ovl.soft.s[tid];
        #pragma unroll
        for (int o = 16; o > 0; o >>= 1) {
            float m2 = __shfl_xor_sync(0xffffffffu, m, o);
            float s2 = __shfl_xor_sync(0xffffffffu, s, o);
            merge_ms(m, s, m2, s2);
        }
        if (tid == 0) { g_m_part[bid] = m; g_s_part[bid] = s; }
    }
    grid_sync(nb);                                      // barrier arrival #1

    {
        float pm = (tid < nb) ? __ldcg(&g_m_part[tid]) : -1e30f;
        float psv = (tid < nb) ? __ldcg(&g_s_part[tid]) : 0.f;
        #pragma unroll
        for (int o = 16; o > 0; o >>= 1) {
            float m2 = __shfl_xor_sync(0xffffffffu, pm, o);
            float s2 = __shfl_xor_sync(0xffffffffu, psv, o);
            merge_ms(pm, psv, m2, s2);
        }
        __syncthreads();
        if (lid == 0) { ovl.soft.m[wid] = pm; ovl.soft.s[wid] = psv; }
        __syncthreads();
        if (tid == 0) {
            float mm = ovl.soft.m[0], ss = ovl.soft.s[0];
            #pragma unroll
            for (int w2 = 1; w2 < 32; w2++) merge_ms(mm, ss, ovl.soft.m[w2], ovl.soft.s[w2]);
            sh_bm = mm; sh_bs = ss;
        }
        __syncthreads();
    }
    const float pmax = sh_bm;
    const float invS = 1.0f / sh_bs;

    // lane l owns row rbase+l forever
    const bool  mine  = (lid < RPW) && (rbase + lid < NITEMS);
    const int   myrow = rbase + lid;
    float myrel = 0.f, myms = 0.f;
    if (mine) {
        myrel = expf(pred[myrow] - pmax) * invS;
        sm_rel[wid * RPW + lid] = myrel;
    }

    // ---------------- A2: normalize -> fp16 into SMEM (zero-fill unowned rows) ----------------
    {
        const float4* Erow = reinterpret_cast<const float4*>(E) + (size_t)rbase * (DIM / 4);
        float4 cur[4];
        if (rbase < NITEMS) {
            #pragma unroll
            for (int j = 0; j < 4; j++) cur[j] = Erow[j * 32 + lid];
        }
        #pragma unroll
        for (int i = 0; i < RPW; i++) {
            int row = rbase + i;
            float4 nxt[4];
            bool have_n = (i + 1 < RPW) && (row + 1 < NITEMS);
            if (have_n) {
                const float4* Er2 = Erow + (size_t)(i + 1) * (DIM / 4);
                #pragma unroll
                for (int j = 0; j < 4; j++) nxt[j] = Er2[j * 32 + lid];
            }
            uint2* Es = reinterpret_cast<uint2*>(sm_rows) + (size_t)(wid * RPW + i) * (DIM / 4);
            if (row < NITEMS) {
                float ss2 = 0.f;
                #pragma unroll
                for (int j = 0; j < 4; j++)
                    ss2 += cur[j].x * cur[j].x + cur[j].y * cur[j].y
                         + cur[j].z * cur[j].z + cur[j].w * cur[j].w;
                ss2 = warp_sum_xor(ss2);
                const float inv = 1.0f / (sqrtf(ss2) + 1e-12f);
                #pragma unroll
                for (int j = 0; j < 4; j++) {
                    __half2 h0 = __floats2half2_rn(cur[j].x * inv, cur[j].y * inv);
                    __half2 h1 = __floats2half2_rn(cur[j].z * inv, cur[j].w * inv);
                    uint2 u;
                    u.x = *reinterpret_cast<unsigned*>(&h0);
                    u.y = *reinterpret_cast<unsigned*>(&h1);
                    Es[j * 32 + lid] = u;
                }
            } else {
                #pragma unroll
                for (int j = 0; j < 4; j++) Es[j * 32 + lid] = make_uint2(0u, 0u);
            }
            #pragma unroll
            for (int j = 0; j < 4; j++) cur[j] = nxt[j];
        }
    }

    // ---------- block argmax for t=0 (score = rel) + publish candidate ----------
    {
        unsigned e = mine ? flip_f(myrel) : 0u;
        unsigned mx = __reduce_max_sync(0xffffffffu, e);
        unsigned ball = __ballot_sync(0xffffffffu, e == mx);
        int src = __ffs(ball) - 1;
        int row = __shfl_sync(0xffffffffu, myrow, src);
        if (lid == 0) { sh_e[wid] = mx; sh_r[wid] = row; }
        __syncthreads();                                 // also fences sm_rows for warp0
        if (wid == 0) {
            unsigned e2 = sh_e[lid];
            int      r2 = sh_r[lid];
            unsigned mx2 = __reduce_max_sync(0xffffffffu, e2);
            unsigned b2  = __ballot_sync(0xffffffffu, e2 == mx2);
            int src2 = __ffs(b2) - 1;
            int row2 = __shfl_sync(0xffffffffu, r2, src2);
            if (mx2 != 0u) {
                int lr = row2 - bid * RPB;
                g_cand[0][bid][lid]      = S4[lr * 64 + lid];
                g_cand[0][bid][32 + lid] = S4[lr * 64 + 32 + lid];
                if (lid == 0) g_candrel[0][bid] = sm_rel[lr];
            }
            __syncwarp();
            if (lid == 0) {
                unsigned long long bb = ((unsigned long long)mx2 << 32) | (unsigned)(~row2);
                if (mx2 != 0u) atomicMax(&g_best[0], bb);
            }
        }
    }
    grid_sync(nb);                                      // barrier arrival #2

    // ---------------- stage winner 0 ----------------
    if (wid == 0) {
        unsigned long long w = 0ull;
        if (lid == 0) w = __ldcg(&g_best[0]);
        w = __shfl_sync(0xffffffffu, w, 0);
        const int idx0 = (int)(~(unsigned int)w);
        const int wbk0 = idx0 / RPB;
        const uint4* Vh = g_cand[0][wbk0];
        ovl.v4[lid]      = __ldcg(Vh + lid);
        ovl.v4[32 + lid] = __ldcg(Vh + 32 + lid);
        if (lid == 0) sh_widx = idx0;
    }
    __syncthreads();

    // err accumulation lives on warp1 lane0 (tid 32), off the critical path
    float err_acc = 0.f, decay_t = 1.0f;
    if (bid == 0 && tid == 32)
        err_acc += __ldcg(&g_candrel[0][sh_widx / RPB]);

    // ---------------- greedy loop: 15 passes ----------------
    for (int t = 0; t < KSEL - 1; t++) {
        const int idx = sh_widx;

        // winner vector from smem staging buffer
        uint4 v0 = ovl.v4[lid];
        uint4 v1 = ovl.v4[32 + lid];
        __half2 vh[8];
        {
            const __half2* p0 = reinterpret_cast<const __half2*>(&v0);
            const __half2* p1 = reinterpret_cast<const __half2*>(&v1);
            #pragma unroll
            for (int q = 0; q < 4; q++) { vh[q] = p0[q]; vh[4 + q] = p1[q]; }
        }

        // 7-row smem GEMV (HFMA2, fp32 cross-chain)
        float f[RPW];
        #pragma unroll
        for (int i = 0; i < RPW; i++) {
            const int lr = wid * RPW + i;
            uint4 a0 = S4[lr * 64 + lid];
            uint4 a1 = S4[lr * 64 + 32 + lid];
            const __half2* h0 = reinterpret_cast<const __half2*>(&a0);
            const __half2* h1 = reinterpret_cast<const __half2*>(&a1);
            __half2 acc_a = __hmul2(h0[0], vh[0]);
            __half2 acc_b = __hmul2(h0[1], vh[1]);
            acc_a = __hfma2(h0[2], vh[2], acc_a);
            acc_b = __hfma2(h0[3], vh[3], acc_b);
            acc_a = __hfma2(h1[0], vh[4], acc_a);
            acc_b = __hfma2(h1[1], vh[5], acc_b);
            acc_a = __hfma2(h1[2], vh[6], acc_a);
            acc_b = __hfma2(h1[3], vh[7], acc_b);
            float2 fa = __half22float2(acc_a);
            float2 fb = __half22float2(acc_b);
            f[i] = (fa.x + fa.y) + (fb.x + fb.y);
        }
        #pragma unroll
        for (int o = 16; o > 0; o >>= 1) {
            #pragma unroll
            for (int i = 0; i < RPW; i++) f[i] += __shfl_xor_sync(0xffffffffu, f[i], o);
        }
        float mysim = 0.f;
        #pragma unroll
        for (int i = 0; i < RPW; i++) if (lid == i) mysim = f[i];

        // score + warp argmax via REDUX
        const float decay_next = decay_t * DECAYF;
        unsigned e = 0u;
        if (mine) {
            myms = (myrow == idx) ? 1e30f : fmaxf(myms, mysim);
            e = flip_f(decay_next * myrel - LAMBDA * myms);
        }
        unsigned mx = __reduce_max_sync(0xffffffffu, e);
        unsigned ball = __ballot_sync(0xffffffffu, e == mx);
        int src = __ffs(ball) - 1;
        int row = __shfl_sync(0xffffffffu, myrow, src);
        if (lid == 0) { sh_e[wid] = mx; sh_r[wid] = row; }
        __syncthreads();                                 // #1

        if (wid == 0) {
            unsigned e2 = sh_e[lid];
            int      r2 = sh_r[lid];
            unsigned mx2 = __reduce_max_sync(0xffffffffu, e2);
            unsigned b2  = __ballot_sync(0xffffffffu, e2 == mx2);
            int src2 = __ffs(b2) - 1;
            int row2 = __shfl_sync(0xffffffffu, r2, src2);
            const int buf = (t + 1) & 1;
            if (mx2 != 0u) {
                int lr = row2 - bid * RPB;
                g_cand[buf][bid][lid]      = S4[lr * 64 + lid];
                g_cand[buf][bid][32 + lid] = S4[lr * 64 + 32 + lid];
                if (lid == 0) g_candrel[buf][bid] = sm_rel[lr];
            }
            __syncwarp();                                // candidate STGs performed (warp scope)
            if (lid == 0) {
                unsigned long long bb = ((unsigned long long)mx2 << 32) | (unsigned)(~row2);
                if (mx2 != 0u) atomicMax(&g_best[t + 1], bb);
                __threadfence();
                unsigned int ticket = atomicAdd(&g_bar, 1u) + 1u;
                unsigned int target = ((ticket + (unsigned)nb - 1u) / (unsigned)nb) * (unsigned)nb;
                while (*((volatile unsigned int*)&g_bar) < target) { }
                __threadfence();
            }
            __syncwarp();
            // stage winner t+1
            unsigned long long w = 0ull;
            if (lid == 0) w = __ldcg(&g_best[t + 1]);
            w = __shfl_sync(0xffffffffu, w, 0);
            const int nidx = (int)(~(unsigned int)w);
            const int nwbk = nidx / RPB;
            if (t + 1 < KSEL - 1) {                      // last winner needs no vector
                const uint4* Vh = g_cand[buf][nwbk];
                ovl.v4[lid]      = __ldcg(Vh + lid);
                ovl.v4[32 + lid] = __ldcg(Vh + 32 + lid);
            }
            if (lid == 0) sh_widx = nidx;
        }
        __syncthreads();                                 // #2 — releases block, ovl/sh_widx ready

        decay_t = decay_next;
        if (bid == 0 && tid == 32)
            err_acc += __ldcg(&g_candrel[(t + 1) & 1][sh_widx / RPB]) * decay_t;
    }

    // mmr_loss = -sum over selected of max_j cos = -sum of diagonal = -KSEL (to fp32)
    if (bid == 0 && tid == 32)
        out[0] = -err_acc - LAMBDA * (float)KSEL;
}

extern "C" void kernel_launch(void* const* d_in, const int* in_sizes, int n_in,
                              void* d_out, int out_size) {
    (void)in_sizes; (void)n_in; (void)out_size;
    const float* pred = (const float*)d_in[0];
    const float* E    = (const float*)d_in[5];   // explanation_embeddings [32768, 512]
    float* out        = (float*)d_out;

    int dev = 0;
    cudaGetDevice(&dev);
    int nsm = 0;
    cudaDeviceGetAttribute(&nsm, cudaDevAttrMultiProcessorCount, dev);
    if (nsm <= 0) nsm = 148;
    if (nsm > MAXB) nsm = MAXB;

    cudaFuncSetAttribute(ranking_kernel,
                         cudaFuncAttributeMaxDynamicSharedMemorySize, SMEM_DYN);
    ranking_kernel<<<nsm, NTHREADS, SMEM_DYN>>>(pred, E, out, nsm);
}

// round 11
// speedup vs baseline: 1.4831x; 1.1158x over previous
#include <cuda_runtime.h>
#include <cuda_fp16.h>
#include <math.h>

#define NITEMS   32768
#define DIM      512
#define KSEL     16
#define LAMBDA   0.5f
#define DECAYF   0.85f
#define NTHREADS 1024
#define MAXB     512
#define RPW      7                      // rows per warp
#define RPB      (32 * RPW)             // 224 rows per block
#define SMEM_DYN (RPB * DIM * 2)        // 229376 B of fp16 rows

// ---------------- device scratch (no allocations allowed) ----------------
struct __align__(16) Slot { unsigned long long best; unsigned cnt; unsigned pad; };

__device__ __align__(16) uint4  g_cand[2][MAXB][64];   // per-block candidate vectors (fp16)
__device__ float                g_candrel[2][MAXB];    // candidate's rel
__device__ float                g_m_part[MAXB];        // online-softmax partial max
__device__ float                g_s_part[MAXB];        // online-softmax partial sum
__device__ Slot                 g_slot[KSEL];          // fused argmax + arrival counter per winner
__device__ unsigned int         g_bar;                 // monotonic barrier (prologue only)

// order-preserving float->u32 (monotone increasing); 0 reserved for "invalid"
__device__ __forceinline__ unsigned flip_f(float s) {
    unsigned b = __float_as_uint(s);
    return (b & 0x80000000u) ? ~b : (b | 0x80000000u);
}
__device__ __forceinline__ float warp_sum_xor(float v) {
    #pragma unroll
    for (int o = 16; o > 0; o >>= 1) v += __shfl_xor_sync(0xffffffffu, v, o);
    return v;
}
__device__ __forceinline__ void merge_ms(float& m, float& s, float m2, float s2) {
    float M = fmaxf(m, m2);
    s = s * expf(m - M) + s2 * expf(m2 - M);
    m = M;
}
// 16B coherent poll: returns final best once cnt == nb (cnt written only after release fence)
__device__ __forceinline__ unsigned long long slot_wait(Slot* sp, unsigned nb) {
    unsigned lo, hi, c, p;
    do {
        asm volatile("ld.volatile.global.v4.u32 {%0,%1,%2,%3}, [%4];"
                     : "=r"(lo), "=r"(hi), "=r"(c), "=r"(p) : "l"(sp));
    } while (c < nb);
    return ((unsigned long long)hi << 32) | lo;
}

__global__ void __launch_bounds__(NTHREADS, 1)
ranking_kernel(const float* __restrict__ pred,
               const float* __restrict__ E,
               float* __restrict__ out,
               int nb)
{
    extern __shared__ __align__(16) __half sm_rows[];   // RPB rows x 512 fp16

    __shared__ __align__(16) uint4 sh_v4[64];           // staged winner vector, 1 KB
    __shared__ unsigned sh_e[32];
    __shared__ int      sh_r[32];
    __shared__ int      sh_widx;
    __shared__ float    sh_bm, sh_bs;
    __shared__ float    sm_rel[RPB];

    const int tid   = threadIdx.x;
    const int bid   = blockIdx.x;
    const int lid   = tid & 31;
    const int wid   = tid >> 5;
    const int rbase = bid * RPB + wid * RPW;
    const int gthreads = nb * NTHREADS;
    const int gtid     = bid * NTHREADS + tid;
    const uint4* S4 = reinterpret_cast<const uint4*>(sm_rows);

    // reset slots (graph-replay safe); ordered before any publish by the
    // prologue arrive's threadfence + softmax barrier wait
    if (bid == 0 && tid == 0) {
        #pragma unroll
        for (int i = 0; i < KSEL; i++) { g_slot[i].best = 0ull; g_slot[i].cnt = 0u; }
    }

    // ---------------- A1: online softmax partials over predictions ----------------
    float m = -1e30f, s = 0.f;
    for (int i = gtid; i < NITEMS; i += gthreads) {
        float p = pred[i];
        float M = fmaxf(m, p);
        s = s * expf(m - M) + expf(p - M);
        m = M;
    }
    #pragma unroll
    for (int o = 16; o > 0; o >>= 1) {
        float m2 = __shfl_xor_sync(0xffffffffu, m, o);
        float s2 = __shfl_xor_sync(0xffffffffu, s, o);
        merge_ms(m, s, m2, s2);
    }
    __syncthreads();
    if (lid == 0) { reinterpret_cast<float*>(sh_v4)[wid] = m; reinterpret_cast<float*>(sh_v4)[32 + wid] = s; }
    __syncthreads();
    if (tid < 32) {
        m = reinterpret_cast<float*>(sh_v4)[tid];
        s = reinterpret_cast<float*>(sh_v4)[32 + tid];
        #pragma unroll
        for (int o = 16; o > 0; o >>= 1) {
            float m2 = __shfl_xor_sync(0xffffffffu, m, o);
            float s2 = __shfl_xor_sync(0xffffffffu, s, o);
            merge_ms(m, s, m2, s2);
        }
        if (tid == 0) { g_m_part[bid] = m; g_s_part[bid] = s; }
    }
    __syncthreads();

    // split-arrive: publish partials now, wait AFTER the big normalize read
    unsigned bar_target = 0u;
    if (tid == 0) {
        __threadfence();
        unsigned tk = atomicAdd(&g_bar, 1u) + 1u;
        bar_target = ((tk + (unsigned)nb - 1u) / (unsigned)nb) * (unsigned)nb;
    }

    // ---------------- A2: normalize -> fp16 into SMEM (overlaps barrier) ----------------
    {
        const float4* Erow = reinterpret_cast<const float4*>(E) + (size_t)rbase * (DIM / 4);
        float4 cur[4];
        if (rbase < NITEMS) {
            #pragma unroll
            for (int j = 0; j < 4; j++) cur[j] = Erow[j * 32 + lid];
        }
        #pragma unroll
        for (int i = 0; i < RPW; i++) {
            int row = rbase + i;
            float4 nxt[4];
            bool have_n = (i + 1 < RPW) && (row + 1 < NITEMS);
            if (have_n) {
                const float4* Er2 = Erow + (size_t)(i + 1) * (DIM / 4);
                #pragma unroll
                for (int j = 0; j < 4; j++) nxt[j] = Er2[j * 32 + lid];
            }
            uint2* Es = reinterpret_cast<uint2*>(sm_rows) + (size_t)(wid * RPW + i) * (DIM / 4);
            if (row < NITEMS) {
                float ss2 = 0.f;
                #pragma unroll
                for (int j = 0; j < 4; j++)
                    ss2 += cur[j].x * cur[j].x + cur[j].y * cur[j].y
                         + cur[j].z * cur[j].z + cur[j].w * cur[j].w;
                ss2 = warp_sum_xor(ss2);
                const float inv = 1.0f / (sqrtf(ss2) + 1e-12f);
                #pragma unroll
                for (int j = 0; j < 4; j++) {
                    __half2 h0 = __floats2half2_rn(cur[j].x * inv, cur[j].y * inv);
                    __half2 h1 = __floats2half2_rn(cur[j].z * inv, cur[j].w * inv);
                    uint2 u;
                    u.x = *reinterpret_cast<unsigned*>(&h0);
                    u.y = *reinterpret_cast<unsigned*>(&h1);
                    Es[j * 32 + lid] = u;
                }
            } else {
                #pragma unroll
                for (int j = 0; j < 4; j++) Es[j * 32 + lid] = make_uint2(0u, 0u);
            }
            #pragma unroll
            for (int j = 0; j < 4; j++) cur[j] = nxt[j];
        }
    }

    // wait for softmax partials from all blocks
    if (tid == 0) {
        while (*((volatile unsigned*)&g_bar) < bar_target) { }
        __threadfence();
    }
    __syncthreads();

    // merge 148 partials: warp0 strided + butterfly
    if (wid == 0) {
        float pm = -1e30f, psv = 0.f;
        for (int j = lid; j < nb; j += 32)
            merge_ms(pm, psv, __ldcg(&g_m_part[j]), __ldcg(&g_s_part[j]));
        #pragma unroll
        for (int o = 16; o > 0; o >>= 1) {
            float m2 = __shfl_xor_sync(0xffffffffu, pm, o);
            float s2 = __shfl_xor_sync(0xffffffffu, psv, o);
            merge_ms(pm, psv, m2, s2);
        }
        if (lid == 0) { sh_bm = pm; sh_bs = psv; }
    }
    __syncthreads();
    const float pmax = sh_bm;
    const float invS = 1.0f / sh_bs;

    // lane l owns row rbase+l forever
    const bool  mine  = (lid < RPW) && (rbase + lid < NITEMS);
    const int   myrow = rbase + lid;
    float myrel = 0.f, myms = 0.f;
    if (mine) {
        myrel = expf(pred[myrow] - pmax) * invS;
        sm_rel[wid * RPW + lid] = myrel;
    }

    // ---------- t=0: block argmax (score = rel), publish slot 0, stage ----------
    {
        unsigned e = mine ? flip_f(myrel) : 0u;
        unsigned mx = __reduce_max_sync(0xffffffffu, e);
        unsigned ball = __ballot_sync(0xffffffffu, e == mx);
        int src = __ffs(ball) - 1;
        int row = __shfl_sync(0xffffffffu, myrow, src);
        if (lid == 0) { sh_e[wid] = mx; sh_r[wid] = row; }
        __syncthreads();                                 // fences sm_rows/sm_rel for warp0
        if (wid == 0) {
            unsigned e2 = sh_e[lid];
            int      r2 = sh_r[lid];
            unsigned mx2 = __reduce_max_sync(0xffffffffu, e2);
            unsigned b2  = __ballot_sync(0xffffffffu, e2 == mx2);
            int src2 = __ffs(b2) - 1;
            int row2 = __shfl_sync(0xffffffffu, r2, src2);
            if (mx2 != 0u) {
                int lr = row2 - bid * RPB;
                g_cand[0][bid][lid]      = S4[lr * 64 + lid];
                g_cand[0][bid][32 + lid] = S4[lr * 64 + 32 + lid];
                if (lid == 0) g_candrel[0][bid] = sm_rel[lr];
            }
            __syncwarp();
            if (lid == 0) {
                if (mx2 != 0u) {
                    unsigned long long bb = ((unsigned long long)mx2 << 32) | (unsigned)(~row2);
                    atomicMax(&g_slot[0].best, bb);      // overlaps STG drain
                }
                __threadfence();                         // release: STGs + max visible
                atomicAdd(&g_slot[0].cnt, 1u);           // arrive
            }
            // wait + stage winner 0 (all lanes poll; broadcast load)
            unsigned long long w = slot_wait(&g_slot[0], (unsigned)nb);
            __threadfence();                             // acquire
            const int idx0 = (int)(~(unsigned int)w);
            const int wbk0 = idx0 / RPB;
            const uint4* Vh = g_cand[0][wbk0];
            sh_v4[lid]      = __ldcg(Vh + lid);
            sh_v4[32 + lid] = __ldcg(Vh + 32 + lid);
            if (lid == 0) sh_widx = idx0;
        }
        __syncthreads();
    }

    // err accumulation on warp1 lane0 (tid 32), off the critical path
    float err_acc = 0.f, decay_t = 1.0f;
    if (bid == 0 && tid == 32)
        err_acc += __ldcg(&g_candrel[0][sh_widx / RPB]);

    // ---------------- greedy loop: 15 passes ----------------
    for (int t = 0; t < KSEL - 1; t++) {
        const int idx = sh_widx;

        uint4 v0 = sh_v4[lid];
        uint4 v1 = sh_v4[32 + lid];
        __half2 vh[8];
        {
            const __half2* p0 = reinterpret_cast<const __half2*>(&v0);
            const __half2* p1 = reinterpret_cast<const __half2*>(&v1);
            #pragma unroll
            for (int q = 0; q < 4; q++) { vh[q] = p0[q]; vh[4 + q] = p1[q]; }
        }

        // 7-row smem GEMV (HFMA2, fp32 cross-chain)
        float f[RPW];
        #pragma unroll
        for (int i = 0; i < RPW; i++) {
            const int lr = wid * RPW + i;
            uint4 a0 = S4[lr * 64 + lid];
            uint4 a1 = S4[lr * 64 + 32 + lid];
            const __half2* h0 = reinterpret_cast<const __half2*>(&a0);
            const __half2* h1 = reinterpret_cast<const __half2*>(&a1);
            __half2 acc_a = __hmul2(h0[0], vh[0]);
            __half2 acc_b = __hmul2(h0[1], vh[1]);
            acc_a = __hfma2(h0[2], vh[2], acc_a);
            acc_b = __hfma2(h0[3], vh[3], acc_b);
            acc_a = __hfma2(h1[0], vh[4], acc_a);
            acc_b = __hfma2(h1[1], vh[5], acc_b);
            acc_a = __hfma2(h1[2], vh[6], acc_a);
            acc_b = __hfma2(h1[3], vh[7], acc_b);
            float2 fa = __half22float2(acc_a);
            float2 fb = __half22float2(acc_b);
            f[i] = (fa.x + fa.y) + (fb.x + fb.y);
        }
        #pragma unroll
        for (int o = 16; o > 0; o >>= 1) {
            #pragma unroll
            for (int i = 0; i < RPW; i++) f[i] += __shfl_xor_sync(0xffffffffu, f[i], o);
        }
        float mysim = 0.f;
        #pragma unroll
        for (int i = 0; i < RPW; i++) if (lid == i) mysim = f[i];

        // score + warp argmax via REDUX
        const float decay_next = decay_t * DECAYF;
        unsigned e = 0u;
        if (mine) {
            myms = (myrow == idx) ? 1e30f : fmaxf(myms, mysim);
            e = flip_f(decay_next * myrel - LAMBDA * myms);
        }
        unsigned mx = __reduce_max_sync(0xffffffffu, e);
        unsigned ball = __ballot_sync(0xffffffffu, e == mx);
        int src = __ffs(ball) - 1;
        int row = __shfl_sync(0xffffffffu, myrow, src);
        if (lid == 0) { sh_e[wid] = mx; sh_r[wid] = row; }
        __syncthreads();                                 // #1

        if (wid == 0) {
            unsigned e2 = sh_e[lid];
            int      r2 = sh_r[lid];
            unsigned mx2 = __reduce_max_sync(0xffffffffu, e2);
            unsigned b2  = __ballot_sync(0xffffffffu, e2 == mx2);
            int src2 = __ffs(b2) - 1;
            int row2 = __shfl_sync(0xffffffffu, r2, src2);
            const int buf = (t + 1) & 1;
            const int k = t + 1;
            if (mx2 != 0u) {
                int lr = row2 - bid * RPB;
                g_cand[buf][bid][lid]      = S4[lr * 64 + lid];
                g_cand[buf][bid][32 + lid] = S4[lr * 64 + 32 + lid];
                if (lid == 0) g_candrel[buf][bid] = sm_rel[lr];
            }
            __syncwarp();
            if (lid == 0) {
                if (mx2 != 0u) {
                    unsigned long long bb = ((unsigned long long)mx2 << 32) | (unsigned)(~row2);
                    atomicMax(&g_slot[k].best, bb);      // overlaps STG drain
                }
                __threadfence();
                atomicAdd(&g_slot[k].cnt, 1u);
            }
            // wait + stage winner k
            unsigned long long w = slot_wait(&g_slot[k], (unsigned)nb);
            __threadfence();
            const int nidx = (int)(~(unsigned int)w);
            const int nwbk = nidx / RPB;
            if (k < KSEL - 1) {                          // last winner needs no vector
                const uint4* Vh = g_cand[buf][nwbk];
                sh_v4[lid]      = __ldcg(Vh + lid);
                sh_v4[32 + lid] = __ldcg(Vh + 32 + lid);
            }
            if (lid == 0) sh_widx = nidx;
        }
        __syncthreads();                                 // #2

        decay_t = decay_next;
        if (bid == 0 && tid == 32)
            err_acc += __ldcg(&g_candrel[(t + 1) & 1][sh_widx / RPB]) * decay_t;
    }

    // mmr_loss = -sum over selected of max_j cos = -sum of diagonal = -KSEL (fp32-exact)
    if (bid == 0 && tid == 32)
        out[0] = -err_acc - LAMBDA * (float)KSEL;
}

extern "C" void kernel_launch(void* const* d_in, const int* in_sizes, int n_in,
                              void* d_out, int out_size) {
    (void)in_sizes; (void)n_in; (void)out_size;
    const float* pred = (const float*)d_in[0];
    const float* E    = (const float*)d_in[5];   // explanation_embeddings [32768, 512]
    float* out        = (float*)d_out;

    int dev = 0;
    cudaGetDevice(&dev);
    int nsm = 0;
    cudaDeviceGetAttribute(&nsm, cudaDevAttrMultiProcessorCount, dev);
    if (nsm <= 0) nsm = 148;
    if (nsm > MAXB) nsm = MAXB;

    cudaFuncSetAttribute(ranking_kernel,
                         cudaFuncAttributeMaxDynamicSharedMemorySize, SMEM_DYN);
    ranking_kernel<<<nsm, NTHREADS, SMEM_DYN>>>(pred, E, out, nsm);
}

// round 13
// speedup vs baseline: 1.5727x; 1.0604x over previous
#include <cuda_runtime.h>
#include <cuda_fp16.h>
#include <math.h>

#define NITEMS   32768
#define DIM      512
#define KSEL     16
#define LAMBDA   0.5f
#define DECAYF   0.85f
#define NTHREADS 1024
#define MAXB     512
#define RPW      7                      // rows per warp
#define RPB      (32 * RPW)             // 224 rows per block
#define SMEM_DYN (RPB * DIM * 2)        // 229376 B of fp16 rows
#define FXSCALE  1048576.0f             // 2^20 fixed-point scale for dot reduce
#define FXINV    (1.0f / 1048576.0f)

// ---------------- device scratch (no allocations allowed) ----------------
struct __align__(16) Slot { unsigned long long best; unsigned cnt; unsigned pad; };

__device__ __align__(16) uint4  g_cand[2][MAXB][64];   // per-block candidate vectors (fp16)
__device__ float                g_candrel[2][MAXB];    // candidate's rel
__device__ float                g_m_part[MAXB];        // online-softmax partial max
__device__ float                g_s_part[MAXB];        // online-softmax partial sum
__device__ Slot                 g_slot[KSEL];          // fused argmax + arrival counter per winner
__device__ unsigned int         g_bar;                 // monotonic barrier (prologue only)

// order-preserving float->u32 (monotone increasing); 0 reserved for "invalid"
__device__ __forceinline__ unsigned flip_f(float s) {
    unsigned b = __float_as_uint(s);
    return (b & 0x80000000u) ? ~b : (b | 0x80000000u);
}
__device__ __forceinline__ float warp_sum_xor(float v) {
    #pragma unroll
    for (int o = 16; o > 0; o >>= 1) v += __shfl_xor_sync(0xffffffffu, v, o);
    return v;
}
__device__ __forceinline__ void merge_ms(float& m, float& s, float m2, float s2) {
    float M = fmaxf(m, m2);
    s = s * expf(m - M) + s2 * expf(m2 - M);
    m = M;
}
// 16B coherent poll: returns final best once cnt == nb (cnt written only after release fence)
__device__ __forceinline__ unsigned long long slot_wait(Slot* sp, unsigned nb) {
    unsigned lo, hi, c, p;
    do {
        asm volatile("ld.volatile.global.v4.u32 {%0,%1,%2,%3}, [%4];"
                     : "=r"(lo), "=r"(hi), "=r"(c), "=r"(p) : "l"(sp));
    } while (c < nb);
    return ((unsigned long long)hi << 32) | lo;
}

__global__ void __launch_bounds__(NTHREADS, 1)
ranking_kernel(const float* __restrict__ pred,
               const float* __restrict__ E,
               float* __restrict__ out,
               int nb)
{
    extern __shared__ __align__(16) __half sm_rows[];   // RPB rows x 512 fp16

    __shared__ __align__(16) uint4 sh_v4[64];           // staged winner vector, 1 KB
    __shared__ unsigned sh_e[32];
    __shared__ int      sh_r[32];
    __shared__ int      sh_widx;
    __shared__ float    sh_bm, sh_bs;
    __shared__ float    sm_rel[RPB];

    const int tid   = threadIdx.x;
    const int bid   = blockIdx.x;
    const int lid   = tid & 31;
    const int wid   = tid >> 5;
    const int rbase = bid * RPB + wid * RPW;
    const int gthreads = nb * NTHREADS;
    const int gtid     = bid * NTHREADS + tid;
    const uint4* S4 = reinterpret_cast<const uint4*>(sm_rows);

    // reset slots (graph-replay safe); ordered before any publish by the
    // prologue arrive's threadfence + softmax barrier wait
    if (bid == 0 && tid == 0) {
        #pragma unroll
        for (int i = 0; i < KSEL; i++) { g_slot[i].best = 0ull; g_slot[i].cnt = 0u; }
    }

    // ---------------- A1: online softmax partials over predictions ----------------
    float m = -1e30f, s = 0.f;
    for (int i = gtid; i < NITEMS; i += gthreads) {
        float p = pred[i];
        float M = fmaxf(m, p);
        s = s * expf(m - M) + expf(p - M);
        m = M;
    }
    #pragma unroll
    for (int o = 16; o > 0; o >>= 1) {
        float m2 = __shfl_xor_sync(0xffffffffu, m, o);
        float s2 = __shfl_xor_sync(0xffffffffu, s, o);
        merge_ms(m, s, m2, s2);
    }
    __syncthreads();
    if (lid == 0) { reinterpret_cast<float*>(sh_v4)[wid] = m; reinterpret_cast<float*>(sh_v4)[32 + wid] = s; }
    __syncthreads();
    if (tid < 32) {
        m = reinterpret_cast<float*>(sh_v4)[tid];
        s = reinterpret_cast<float*>(sh_v4)[32 + tid];
        #pragma unroll
        for (int o = 16; o > 0; o >>= 1) {
            float m2 = __shfl_xor_sync(0xffffffffu, m, o);
            float s2 = __shfl_xor_sync(0xffffffffu, s, o);
            merge_ms(m, s, m2, s2);
        }
        if (tid == 0) { g_m_part[bid] = m; g_s_part[bid] = s; }
    }
    __syncthreads();

    // split-arrive: publish partials now, wait AFTER the big normalize read
    unsigned bar_target = 0u;
    if (tid == 0) {
        __threadfence();
        unsigned tk = atomicAdd(&g_bar, 1u) + 1u;
        bar_target = ((tk + (unsigned)nb - 1u) / (unsigned)nb) * (unsigned)nb;
    }

    // ---------------- A2: normalize -> fp16 into SMEM (overlaps barrier) ----------------
    {
        const float4* Erow = reinterpret_cast<const float4*>(E) + (size_t)rbase * (DIM / 4);
        float4 cur[4];
        if (rbase < NITEMS) {
            #pragma unroll
            for (int j = 0; j < 4; j++) cur[j] = Erow[j * 32 + lid];
        }
        #pragma unroll
        for (int i = 0; i < RPW; i++) {
            int row = rbase + i;
            float4 nxt[4];
            bool have_n = (i + 1 < RPW) && (row + 1 < NITEMS);
            if (have_n) {
                const float4* Er2 = Erow + (size_t)(i + 1) * (DIM / 4);
                #pragma unroll
                for (int j = 0; j < 4; j++) nxt[j] = Er2[j * 32 + lid];
            }
            uint2* Es = reinterpret_cast<uint2*>(sm_rows) + (size_t)(wid * RPW + i) * (DIM / 4);
            if (row < NITEMS) {
                float ss2 = 0.f;
                #pragma unroll
                for (int j = 0; j < 4; j++)
                    ss2 += cur[j].x * cur[j].x + cur[j].y * cur[j].y
                         + cur[j].z * cur[j].z + cur[j].w * cur[j].w;
                ss2 = warp_sum_xor(ss2);
                const float inv = 1.0f / (sqrtf(ss2) + 1e-12f);
                #pragma unroll
                for (int j = 0; j < 4; j++) {
                    __half2 h0 = __floats2half2_rn(cur[j].x * inv, cur[j].y * inv);
                    __half2 h1 = __floats2half2_rn(cur[j].z * inv, cur[j].w * inv);
                    uint2 u;
                    u.x = *reinterpret_cast<unsigned*>(&h0);
                    u.y = *reinterpret_cast<unsigned*>(&h1);
                    Es[j * 32 + lid] = u;
                }
            } else {
                #pragma unroll
                for (int j = 0; j < 4; j++) Es[j * 32 + lid] = make_uint2(0u, 0u);
            }
            #pragma unroll
            for (int j = 0; j < 4; j++) cur[j] = nxt[j];
        }
    }

    // wait for softmax partials from all blocks
    if (tid == 0) {
        while (*((volatile unsigned*)&g_bar) < bar_target) { }
        __threadfence();
    }
    __syncthreads();

    // merge 148 partials: warp0 strided + butterfly
    if (wid == 0) {
        float pm = -1e30f, psv = 0.f;
        for (int j = lid; j < nb; j += 32)
            merge_ms(pm, psv, __ldcg(&g_m_part[j]), __ldcg(&g_s_part[j]));
        #pragma unroll
        for (int o = 16; o > 0; o >>= 1) {
            float m2 = __shfl_xor_sync(0xffffffffu, pm, o);
            float s2 = __shfl_xor_sync(0xffffffffu, psv, o);
            merge_ms(pm, psv, m2, s2);
        }
        if (lid == 0) { sh_bm = pm; sh_bs = psv; }
    }
    __syncthreads();
    const float pmax = sh_bm;
    const float invS = 1.0f / sh_bs;

    // lane l owns row rbase+l forever
    const bool  mine  = (lid < RPW) && (rbase + lid < NITEMS);
    const int   myrow = rbase + lid;
    float myrel = 0.f, myms = 0.f;
    if (mine) {
        myrel = expf(pred[myrow] - pmax) * invS;
        sm_rel[wid * RPW + lid] = myrel;
    }

    // ---------- t=0: block argmax (score = rel), publish slot 0, stage ----------
    {
        unsigned e = mine ? flip_f(myrel) : 0u;
        unsigned mx = __reduce_max_sync(0xffffffffu, e);
        unsigned ball = __ballot_sync(0xffffffffu, e == mx);
        int src = __ffs(ball) - 1;
        int row = __shfl_sync(0xffffffffu, myrow, src);
        if (lid == 0) { sh_e[wid] = mx; sh_r[wid] = row; }
        __syncthreads();                                 // fences sm_rows/sm_rel for warp0
        if (wid == 0) {
            unsigned e2 = sh_e[lid];
            int      r2 = sh_r[lid];
            unsigned mx2 = __reduce_max_sync(0xffffffffu, e2);
            unsigned b2  = __ballot_sync(0xffffffffu, e2 == mx2);
            int src2 = __ffs(b2) - 1;
            int row2 = __shfl_sync(0xffffffffu, r2, src2);
            if (mx2 != 0u) {
                int lr = row2 - bid * RPB;
                g_cand[0][bid][lid]      = S4[lr * 64 + lid];
                g_cand[0][bid][32 + lid] = S4[lr * 64 + 32 + lid];
                if (lid == 0) g_candrel[0][bid] = sm_rel[lr];
            }
            __syncwarp();
            if (lid == 0) {
                if (mx2 != 0u) {
                    unsigned long long bb = ((unsigned long long)mx2 << 32) | (unsigned)(~row2);
                    atomicMax(&g_slot[0].best, bb);      // overlaps STG drain
                }
                __threadfence();                         // release: STGs + max visible
                atomicAdd(&g_slot[0].cnt, 1u);           // arrive
            }
            // wait + stage winner 0 (all lanes poll; broadcast load)
            unsigned long long w = slot_wait(&g_slot[0], (unsigned)nb);
            __threadfence();                             // acquire
            const int idx0 = (int)(~(unsigned int)w);
            const int wbk0 = idx0 / RPB;
            const uint4* Vh = g_cand[0][wbk0];
            sh_v4[lid]      = __ldcg(Vh + lid);
            sh_v4[32 + lid] = __ldcg(Vh + 32 + lid);
            if (lid == 0) sh_widx = idx0;
        }
        __syncthreads();
    }

    // err accumulation on warp1 lane0 (tid 32), off the critical path
    float err_acc = 0.f, decay_t = 1.0f;
    if (bid == 0 && tid == 32)
        err_acc += __ldcg(&g_candrel[0][sh_widx / RPB]);

    // ---------------- greedy loop: 15 passes ----------------
    for (int t = 0; t < KSEL - 1; t++) {
        const int idx = sh_widx;

        uint4 v0 = sh_v4[lid];
        uint4 v1 = sh_v4[32 + lid];
        __half2 vh[8];
        {
            const __half2* p0 = reinterpret_cast<const __half2*>(&v0);
            const __half2* p1 = reinterpret_cast<const __half2*>(&v1);
            #pragma unroll
            for (int q = 0; q < 4; q++) { vh[q] = p0[q]; vh[4 + q] = p1[q]; }
        }

        // 7-row smem GEMV: HFMA2 partials + ONE s32 REDUX per row (2^20 fixed point;
        // |partial| <= 16 so 32-lane sum <= 2^29, no overflow; quant err ~1.5e-5 << fp16 noise)
        float mysim = 0.f;
        #pragma unroll
        for (int i = 0; i < RPW; i++) {
            const int lr = wid * RPW + i;
            uint4 a0 = S4[lr * 64 + lid];
            uint4 a1 = S4[lr * 64 + 32 + lid];
            const __half2* h0 = reinterpret_cast<const __half2*>(&a0);
            const __half2* h1 = reinterpret_cast<const __half2*>(&a1);
            __half2 acc_a = __hmul2(h0[0], vh[0]);
            __half2 acc_b = __hmul2(h0[1], vh[1]);
            acc_a = __hfma2(h0[2], vh[2], acc_a);
            acc_b = __hfma2(h0[3], vh[3], acc_b);
            acc_a = __hfma2(h1[0], vh[4], acc_a);
            acc_b = __hfma2(h1[1], vh[5], acc_b);
            acc_a = __hfma2(h1[2], vh[6], acc_a);
            acc_b = __hfma2(h1[3], vh[7], acc_b);
            float2 fa = __half22float2(acc_a);
            float2 fb = __half22float2(acc_b);
            float p = (fa.x + fa.y) + (fb.x + fb.y);
            int   pi = __float2int_rn(p * FXSCALE);
            int   ss = (int)__reduce_add_sync(0xffffffffu, (unsigned)pi);
            if (lid == i) mysim = (float)ss * FXINV;
        }

        // score + warp argmax via REDUX
        const float decay_next = decay_t * DECAYF;
        unsigned e = 0u;
        if (mine) {
            myms = (myrow == idx) ? 1e30f : fmaxf(myms, mysim);
            e = flip_f(decay_next * myrel - LAMBDA * myms);
        }
        unsigned mx = __reduce_max_sync(0xffffffffu, e);
        unsigned ball = __ballot_sync(0xffffffffu, e == mx);
        int src = __ffs(ball) - 1;
        int row = __shfl_sync(0xffffffffu, myrow, src);
        if (lid == 0) { sh_e[wid] = mx; sh_r[wid] = row; }
        __syncthreads();                                 // #1

        if (wid == 0) {
            unsigned e2 = sh_e[lid];
            int      r2 = sh_r[lid];
            unsigned mx2 = __reduce_max_sync(0xffffffffu, e2);
            unsigned b2  = __ballot_sync(0xffffffffu, e2 == mx2);
            int src2 = __ffs(b2) - 1;
            int row2 = __shfl_sync(0xffffffffu, r2, src2);
            const int buf = (t + 1) & 1;
            const int k = t + 1;
            if (mx2 != 0u) {
                int lr = row2 - bid * RPB;
                g_cand[buf][bid][lid]      = S4[lr * 64 + lid];
                g_cand[buf][bid][32 + lid] = S4[lr * 64 + 32 + lid];
                if (lid == 0) g_candrel[buf][bid] = sm_rel[lr];
            }
            __syncwarp();
            if (lid == 0) {
                if (mx2 != 0u) {
                    unsigned long long bb = ((unsigned long long)mx2 << 32) | (unsigned)(~row2);
                    atomicMax(&g_slot[k].best, bb);      // overlaps STG drain
                }
                __threadfence();
                atomicAdd(&g_slot[k].cnt, 1u);
            }
            // wait + stage winner k
            unsigned long long w = slot_wait(&g_slot[k], (unsigned)nb);
            __threadfence();
            const int nidx = (int)(~(unsigned int)w);
            const int nwbk = nidx / RPB;
            if (k < KSEL - 1) {                          // last winner needs no vector
                const uint4* Vh = g_cand[buf][nwbk];
                sh_v4[lid]      = __ldcg(Vh + lid);
                sh_v4[32 + lid] = __ldcg(Vh + 32 + lid);
            }
            if (lid == 0) sh_widx = nidx;
        }
        __syncthreads();                                 // #2

        decay_t = decay_next;
        if (bid == 0 && tid == 32)
            err_acc += __ldcg(&g_candrel[(t + 1) & 1][sh_widx / RPB]) * decay_t;
    }

    // mmr_loss = -sum over selected of max_j cos = -sum of diagonal = -KSEL (fp32-exact)
    if (bid == 0 && tid == 32)
        out[0] = -err_acc - LAMBDA * (float)KSEL;
}

extern "C" void kernel_launch(void* const* d_in, const int* in_sizes, int n_in,
                              void* d_out, int out_size) {
    (void)in_sizes; (void)n_in; (void)out_size;
    const float* pred = (const float*)d_in[0];
    const float* E    = (const float*)d_in[5];   // explanation_embeddings [32768, 512]
    float* out        = (float*)d_out;

    int dev = 0;
    cudaGetDevice(&dev);
    int nsm = 0;
    cudaDeviceGetAttribute(&nsm, cudaDevAttrMultiProcessorCount, dev);
    if (nsm <= 0) nsm = 148;
    if (nsm > MAXB) nsm = MAXB;

    cudaFuncSetAttribute(ranking_kernel,
                         cudaFuncAttributeMaxDynamicSharedMemorySize, SMEM_DYN);
    ranking_kernel<<<nsm, NTHREADS, SMEM_DYN>>>(pred, E, out, nsm);
}

// round 14
// speedup vs baseline: 1.6781x; 1.0670x over previous
#include <cuda_runtime.h>
#include <cuda_fp16.h>
#include <math.h>

#define NITEMS   32768
#define DIM      512
#define KSEL     16
#define LAMBDA   0.5f
#define DECAYF   0.85f
#define NTHREADS 1024
#define MAXB     512
#define RPW      7                      // rows per warp
#define RPB      (32 * RPW)             // 224 rows per block
#define SMEM_DYN (RPB * DIM)            // 114688 B of int8 rows

// ---------------- device scratch (no allocations allowed) ----------------
struct __align__(16) Slot { unsigned long long best; unsigned cnt; unsigned pad; };

__device__ __align__(16) uint4  g_cand[2][MAXB][32];   // per-block candidate vectors (int8, 512 B)
__device__ __align__(8)  float2 g_candinfo[2][MAXB];   // (rel, inv_scale) of candidate
__device__ float                g_m_part[MAXB];        // online-softmax partial max
__device__ float                g_s_part[MAXB];        // online-softmax partial sum
__device__ Slot                 g_slot[KSEL];          // fused argmax + arrival counter per winner
__device__ unsigned int         g_bar;                 // monotonic barrier (prologue only)

// order-preserving float->u32 (monotone increasing); 0 reserved for "invalid"
__device__ __forceinline__ unsigned flip_f(float s) {
    unsigned b = __float_as_uint(s);
    return (b & 0x80000000u) ? ~b : (b | 0x80000000u);
}
__device__ __forceinline__ float warp_sum_xor(float v) {
    #pragma unroll
    for (int o = 16; o > 0; o >>= 1) v += __shfl_xor_sync(0xffffffffu, v, o);
    return v;
}
__device__ __forceinline__ void merge_ms(float& m, float& s, float m2, float s2) {
    float M = fmaxf(m, m2);
    s = s * expf(m - M) + s2 * expf(m2 - M);
    m = M;
}
// 16B coherent poll: returns final best once cnt == nb (cnt written only after release fence)
__device__ __forceinline__ unsigned long long slot_wait(Slot* sp, unsigned nb) {
    unsigned lo, hi, c, p;
    do {
        asm volatile("ld.volatile.global.v4.u32 {%0,%1,%2,%3}, [%4];"
                     : "=r"(lo), "=r"(hi), "=r"(c), "=r"(p) : "l"(sp));
    } while (c < nb);
    return ((unsigned long long)hi << 32) | lo;
}
__device__ __forceinline__ unsigned pack4_s8(int a, int b, int c, int d) {
    return (unsigned)(a & 0xFF) | ((unsigned)(b & 0xFF) << 8)
         | ((unsigned)(c & 0xFF) << 16) | ((unsigned)(d & 0xFF) << 24);
}

__global__ void __launch_bounds__(NTHREADS, 1)
ranking_kernel(const float* __restrict__ pred,
               const float* __restrict__ E,
               float* __restrict__ out,
               int nb)
{
    extern __shared__ __align__(16) char sm_rows[];     // RPB rows x 512 int8

    __shared__ __align__(16) uint4 sh_v4[32];           // staged winner vector, 512 B
    __shared__ unsigned sh_e[32];
    __shared__ int      sh_r[32];
    __shared__ int      sh_widx;
    __shared__ float    sh_vinv;                        // winner's inv scale
    __shared__ float    sh_bm, sh_bs;
    __shared__ float    sm_rel[RPB];
    __shared__ float    sm_inv[RPB];

    const int tid   = threadIdx.x;
    const int bid   = blockIdx.x;
    const int lid   = tid & 31;
    const int wid   = tid >> 5;
    const int rbase = bid * RPB + wid * RPW;
    const int gthreads = nb * NTHREADS;
    const int gtid     = bid * NTHREADS + tid;
    uint4* S4 = reinterpret_cast<uint4*>(sm_rows);      // row lr = S4[lr*32 + lane]

    // reset slots (graph-replay safe); ordered before any publish by the
    // prologue arrive's threadfence + softmax barrier wait
    if (bid == 0 && tid == 0) {
        #pragma unroll
        for (int i = 0; i < KSEL; i++) { g_slot[i].best = 0ull; g_slot[i].cnt = 0u; }
    }

    // ---------------- A1: online softmax partials over predictions ----------------
    float m = -1e30f, s = 0.f;
    for (int i = gtid; i < NITEMS; i += gthreads) {
        float p = pred[i];
        float M = fmaxf(m, p);
        s = s * expf(m - M) + expf(p - M);
        m = M;
    }
    #pragma unroll
    for (int o = 16; o > 0; o >>= 1) {
        float m2 = __shfl_xor_sync(0xffffffffu, m, o);
        float s2 = __shfl_xor_sync(0xffffffffu, s, o);
        merge_ms(m, s, m2, s2);
    }
    __syncthreads();
    if (lid == 0) { reinterpret_cast<float*>(sh_v4)[wid] = m; reinterpret_cast<float*>(sh_v4)[32 + wid] = s; }
    __syncthreads();
    if (tid < 32) {
        m = reinterpret_cast<float*>(sh_v4)[tid];
        s = reinterpret_cast<float*>(sh_v4)[32 + tid];
        #pragma unroll
        for (int o = 16; o > 0; o >>= 1) {
            float m2 = __shfl_xor_sync(0xffffffffu, m, o);
            float s2 = __shfl_xor_sync(0xffffffffu, s, o);
            merge_ms(m, s, m2, s2);
        }
        if (tid == 0) { g_m_part[bid] = m; g_s_part[bid] = s; }
    }
    __syncthreads();

    // split-arrive: publish partials now, wait AFTER the big normalize read
    unsigned bar_target = 0u;
    if (tid == 0) {
        __threadfence();
        unsigned tk = atomicAdd(&g_bar, 1u) + 1u;
        bar_target = ((tk + (unsigned)nb - 1u) / (unsigned)nb) * (unsigned)nb;
    }

    // ---------------- A2: normalize -> per-row-scaled int8 into SMEM ----------------
    float my_inva = 0.f;                                // lane i keeps row rbase+i's inv scale
    {
        const float4* Erow = reinterpret_cast<const float4*>(E) + (size_t)rbase * (DIM / 4);
        float4 cur[4];
        if (rbase < NITEMS) {
            #pragma unroll
            for (int j = 0; j < 4; j++) cur[j] = Erow[j * 32 + lid];
        }
        #pragma unroll
        for (int i = 0; i < RPW; i++) {
            int row = rbase + i;
            const int lr = wid * RPW + i;
            float4 nxt[4];
            bool have_n = (i + 1 < RPW) && (row + 1 < NITEMS);
            if (have_n) {
                const float4* Er2 = Erow + (size_t)(i + 1) * (DIM / 4);
                #pragma unroll
                for (int j = 0; j < 4; j++) nxt[j] = Er2[j * 32 + lid];
            }
            if (row < NITEMS) {
                float ss2 = 0.f;
                #pragma unroll
                for (int j = 0; j < 4; j++)
                    ss2 += cur[j].x * cur[j].x + cur[j].y * cur[j].y
                         + cur[j].z * cur[j].z + cur[j].w * cur[j].w;
                ss2 = warp_sum_xor(ss2);
                const float inv = 1.0f / (sqrtf(ss2) + 1e-12f);
                // normalized elements for this lane
                float xv[16];
                #pragma unroll
                for (int j = 0; j < 4; j++) {
                    xv[j * 4 + 0] = cur[j].x * inv;
                    xv[j * 4 + 1] = cur[j].y * inv;
                    xv[j * 4 + 2] = cur[j].z * inv;
                    xv[j * 4 + 3] = cur[j].w * inv;
                }
                // row max |x| via u32 redux (positive floats order as uints)
                float am = 0.f;
                #pragma unroll
                for (int q = 0; q < 16; q++) am = fmaxf(am, fabsf(xv[q]));
                unsigned amu = __reduce_max_sync(0xffffffffu, __float_as_uint(am));
                float xmax = __uint_as_float(amu);
                float scale = 127.0f / xmax;
                float inva  = xmax * (1.0f / 127.0f);
                // quantize + pack 16 int8 -> uint4
                int q[16];
                #pragma unroll
                for (int t2 = 0; t2 < 16; t2++) q[t2] = __float2int_rn(xv[t2] * scale);
                uint4 u;
                u.x = pack4_s8(q[0],  q[1],  q[2],  q[3]);
                u.y = pack4_s8(q[4],  q[5],  q[6],  q[7]);
                u.z = pack4_s8(q[8],  q[9],  q[10], q[11]);
                u.w = pack4_s8(q[12], q[13], q[14], q[15]);
                S4[lr * 32 + lid] = u;
                if (lid == 0) sm_inv[lr] = inva;
                if (lid == i) my_inva = inva;
            } else {
                S4[lr * 32 + lid] = make_uint4(0u, 0u, 0u, 0u);
                if (lid == 0) sm_inv[lr] = 0.f;
            }
            #pragma unroll
            for (int j = 0; j < 4; j++) cur[j] = nxt[j];
        }
    }

    // wait for softmax partials from all blocks
    if (tid == 0) {
        while (*((volatile unsigned*)&g_bar) < bar_target) { }
        __threadfence();
    }
    __syncthreads();

    // merge 148 partials: warp0 strided + butterfly
    if (wid == 0) {
        float pm = -1e30f, psv = 0.f;
        for (int j = lid; j < nb; j += 32)
            merge_ms(pm, psv, __ldcg(&g_m_part[j]), __ldcg(&g_s_part[j]));
        #pragma unroll
        for (int o = 16; o > 0; o >>= 1) {
            float m2 = __shfl_xor_sync(0xffffffffu, pm, o);
            float s2 = __shfl_xor_sync(0xffffffffu, psv, o);
            merge_ms(pm, psv, m2, s2);
        }
        if (lid == 0) { sh_bm = pm; sh_bs = psv; }
    }
    __syncthreads();
    const float pmax = sh_bm;
    const float invS = 1.0f / sh_bs;

    // lane l owns row rbase+l forever
    const bool  mine  = (lid < RPW) && (rbase + lid < NITEMS);
    const int   myrow = rbase + lid;
    float myrel = 0.f, myms = 0.f;
    if (mine) {
        myrel = expf(pred[myrow] - pmax) * invS;
        sm_rel[wid * RPW + lid] = myrel;
    }

    // ---------- t=0: block argmax (score = rel), publish slot 0, stage ----------
    {
        unsigned e = mine ? flip_f(myrel) : 0u;
        unsigned mx = __reduce_max_sync(0xffffffffu, e);
        unsigned ball = __ballot_sync(0xffffffffu, e == mx);
        int src = __ffs(ball) - 1;
        int row = __shfl_sync(0xffffffffu, myrow, src);
        if (lid == 0) { sh_e[wid] = mx; sh_r[wid] = row; }
        __syncthreads();                                 // fences sm_rows/sm_rel/sm_inv for warp0
        if (wid == 0) {
            unsigned e2 = sh_e[lid];
            int      r2 = sh_r[lid];
            unsigned mx2 = __reduce_max_sync(0xffffffffu, e2);
            unsigned b2  = __ballot_sync(0xffffffffu, e2 == mx2);
            int src2 = __ffs(b2) - 1;
            int row2 = __shfl_sync(0xffffffffu, r2, src2);
            if (mx2 != 0u) {
                int lr = row2 - bid * RPB;
                g_cand[0][bid][lid] = S4[lr * 32 + lid];
                if (lid == 0) g_candinfo[0][bid] = make_float2(sm_rel[lr], sm_inv[lr]);
            }
            __syncwarp();
            if (lid == 0) {
                if (mx2 != 0u) {
                    unsigned long long bb = ((unsigned long long)mx2 << 32) | (unsigned)(~row2);
                    atomicMax(&g_slot[0].best, bb);      // overlaps STG drain
                }
                __threadfence();                         // release: STGs + max visible
                atomicAdd(&g_slot[0].cnt, 1u);           // arrive
            }
            // wait + stage winner 0
            unsigned long long w = slot_wait(&g_slot[0], (unsigned)nb);
            __threadfence();                             // acquire
            const int idx0 = (int)(~(unsigned int)w);
            const int wbk0 = idx0 / RPB;
            sh_v4[lid] = __ldcg(&g_cand[0][wbk0][lid]);
            if (lid == 0) {
                float2 ci = __ldcg(&g_candinfo[0][wbk0]);
                sh_vinv = ci.y;
                sh_widx = idx0;
            }
        }
        __syncthreads();
    }

    // err accumulation on warp1 lane0 (tid 32), off the critical path
    float err_acc = 0.f, decay_t = 1.0f;
    if (bid == 0 && tid == 32)
        err_acc += __ldcg(&g_candinfo[0][sh_widx / RPB]).x;

    // ---------------- greedy loop: 15 passes ----------------
    for (int t = 0; t < KSEL - 1; t++) {
        const int idx = sh_widx;
        const float vinv = sh_vinv;
        const uint4 vv = sh_v4[lid];                     // v bytes 16*lid .. 16*lid+15

        // 7-row int8 GEMV: per row 1 LDS.128 + 4 DP4A + 1 s32 REDUX (exact int sum)
        int acc[RPW];
        #pragma unroll
        for (int i = 0; i < RPW; i++) {
            const int lr = wid * RPW + i;
            uint4 a = S4[lr * 32 + lid];
            int d = __dp4a((int)a.x, (int)vv.x, 0);
            d = __dp4a((int)a.y, (int)vv.y, d);
            d = __dp4a((int)a.z, (int)vv.z, d);
            acc[i] = __dp4a((int)a.w, (int)vv.w, d);
        }
        float mysim = 0.f;
        #pragma unroll
        for (int i = 0; i < RPW; i++) {
            int ss = (int)__reduce_add_sync(0xffffffffu, (unsigned)acc[i]);
            if (lid == i) mysim = (float)ss * my_inva * vinv;
        }

        // score + warp argmax via REDUX
        const float decay_next = decay_t * DECAYF;
        unsigned e = 0u;
        if (mine) {
            myms = (myrow == idx) ? 1e30f : fmaxf(myms, mysim);
            e = flip_f(decay_next * myrel - LAMBDA * myms);
        }
        unsigned mx = __reduce_max_sync(0xffffffffu, e);
        unsigned ball = __ballot_sync(0xffffffffu, e == mx);
        int src = __ffs(ball) - 1;
        int row = __shfl_sync(0xffffffffu, myrow, src);
        if (lid == 0) { sh_e[wid] = mx; sh_r[wid] = row; }
        __syncthreads();                                 // #1

        if (wid == 0) {
            unsigned e2 = sh_e[lid];
            int      r2 = sh_r[lid];
            unsigned mx2 = __reduce_max_sync(0xffffffffu, e2);
            unsigned b2  = __ballot_sync(0xffffffffu, e2 == mx2);
            int src2 = __ffs(b2) - 1;
            int row2 = __shfl_sync(0xffffffffu, r2, src2);
            const int buf = (t + 1) & 1;
            const int k = t + 1;
            if (mx2 != 0u) {
                int lr = row2 - bid * RPB;
                g_cand[buf][bid][lid] = S4[lr * 32 + lid];
                if (lid == 0) g_candinfo[buf][bid] = make_float2(sm_rel[lr], sm_inv[lr]);
            }
            __syncwarp();
            if (lid == 0) {
                if (mx2 != 0u) {
                    unsigned long long bb = ((unsigned long long)mx2 << 32) | (unsigned)(~row2);
                    atomicMax(&g_slot[k].best, bb);      // overlaps STG drain
                }
                __threadfence();
                atomicAdd(&g_slot[k].cnt, 1u);
            }
            // wait + stage winner k
            unsigned long long w = slot_wait(&g_slot[k], (unsigned)nb);
            __threadfence();
            const int nidx = (int)(~(unsigned int)w);
            const int nwbk = nidx / RPB;
            if (k < KSEL - 1) {                          // last winner needs no vector
                sh_v4[lid] = __ldcg(&g_cand[buf][nwbk][lid]);
                if (lid == 0) {
                    float2 ci = __ldcg(&g_candinfo[buf][nwbk]);
                    sh_vinv = ci.y;
                }
            }
            if (lid == 0) sh_widx = nidx;
        }
        __syncthreads();                                 // #2

        decay_t = decay_next;
        if (bid == 0 && tid == 32)
            err_acc += __ldcg(&g_candinfo[(t + 1) & 1][sh_widx / RPB]).x * decay_t;
    }

    // mmr_loss = -sum over selected of max_j cos = -sum of diagonal = -KSEL (fp32-exact)
    if (bid == 0 && tid == 32)
        out[0] = -err_acc - LAMBDA * (float)KSEL;
}

extern "C" void kernel_launch(void* const* d_in, const int* in_sizes, int n_in,
                              void* d_out, int out_size) {
    (void)in_sizes; (void)n_in; (void)out_size;
    const float* pred = (const float*)d_in[0];
    const float* E    = (const float*)d_in[5];   // explanation_embeddings [32768, 512]
    float* out        = (float*)d_out;

    int dev = 0;
    cudaGetDevice(&dev);
    int nsm = 0;
    cudaDeviceGetAttribute(&nsm, cudaDevAttrMultiProcessorCount, dev);
    if (nsm <= 0) nsm = 148;
    if (nsm > MAXB) nsm = MAXB;

    cudaFuncSetAttribute(ranking_kernel,
                         cudaFuncAttributeMaxDynamicSharedMemorySize, SMEM_DYN);
    ranking_kernel<<<nsm, NTHREADS, SMEM_DYN>>>(pred, E, out, nsm);
}

// round 15
// speedup vs baseline: 1.7340x; 1.0333x over previous
#include <cuda_runtime.h>
#include <math.h>

#define NITEMS   32768
#define DIM      512
#define KSEL     16
#define LAMBDA   0.5f
#define DECAYF   0.85f
#define NTHREADS 512
#define WPB      16                     // warps per block
#define RPW      14                     // rows per warp (in registers)
#define RPB      (WPB * RPW)            // 224 rows per block; 148*224 = 33152 >= 32768
#define MAXB     512
#define NGW      (MAXB * WPB)

// ---------------- device scratch (no allocations allowed) ----------------
struct __align__(16) Slot { unsigned long long best; unsigned cnt; unsigned pad; };

__device__ __align__(16) uint4  g_wcand[2][NGW][32];   // per-warp speculative candidate rows (int8)
__device__ __align__(8)  float2 g_winfo[2][NGW];       // (rel, inv_scale) of warp candidate
__device__ float                g_m_part[MAXB];        // online-softmax partial max
__device__ float                g_s_part[MAXB];        // online-softmax partial sum
__device__ Slot                 g_slot[KSEL];          // fused argmax + arrival counter per winner
__device__ unsigned int         g_bar;                 // monotonic barrier (replay-safe slot-reset guard)

// order-preserving float->u32 (monotone increasing); 0 reserved for "invalid"
__device__ __forceinline__ unsigned flip_f(float s) {
    unsigned b = __float_as_uint(s);
    return (b & 0x80000000u) ? ~b : (b | 0x80000000u);
}
__device__ __forceinline__ float warp_sum_xor(float v) {
    #pragma unroll
    for (int o = 16; o > 0; o >>= 1) v += __shfl_xor_sync(0xffffffffu, v, o);
    return v;
}
__device__ __forceinline__ void merge_ms(float& m, float& s, float m2, float s2) {
    float M = fmaxf(m, m2);
    s = s * expf(m - M) + s2 * expf(m2 - M);
    m = M;
}
// 16B coherent poll: returns final best once cnt == nb (cnt written only after release fence)
__device__ __forceinline__ unsigned long long slot_wait(Slot* sp, unsigned nb) {
    unsigned lo, hi, c, p;
    do {
        asm volatile("ld.volatile.global.v4.u32 {%0,%1,%2,%3}, [%4];"
                     : "=r"(lo), "=r"(hi), "=r"(c), "=r"(p) : "l"(sp));
    } while (c < nb);
    return ((unsigned long long)hi << 32) | lo;
}
__device__ __forceinline__ unsigned pack4_s8(int a, int b, int c, int d) {
    return (unsigned)(a & 0xFF) | ((unsigned)(b & 0xFF) << 8)
         | ((unsigned)(c & 0xFF) << 16) | ((unsigned)(d & 0xFF) << 24);
}

__global__ void __launch_bounds__(NTHREADS, 1)
ranking_kernel(const float* __restrict__ pred,
               const float* __restrict__ E,
               float* __restrict__ out,
               int nb)
{
    __shared__ __align__(16) uint4 sh_v4[32];           // staged winner vector, 512 B
    __shared__ unsigned sh_e[WPB];
    __shared__ int      sh_r[WPB];
    __shared__ int      sh_widx;
    __shared__ float    sh_vinv, sh_bm, sh_bs;
    __shared__ float    sh_m[WPB], sh_s[WPB];

    const int tid   = threadIdx.x;
    const int bid   = blockIdx.x;
    const int lid   = tid & 31;
    const int wid   = tid >> 5;
    const int rbase = bid * RPB + wid * RPW;
    const int gw    = bid * WPB + wid;
    const int gthreads = nb * NTHREADS;
    const int gtid     = bid * NTHREADS + tid;

    // reset slots (graph-replay safe); guarded by g_bar before any slot use
    if (bid == 0 && tid == 0) {
        #pragma unroll
        for (int i = 0; i < KSEL; i++) { g_slot[i].best = 0ull; g_slot[i].cnt = 0u; }
    }

    // ---------------- A1: online softmax partials over predictions ----------------
    float m = -1e30f, s = 0.f;
    for (int i = gtid; i < NITEMS; i += gthreads) {
        float p = pred[i];
        float M = fmaxf(m, p);
        s = s * expf(m - M) + expf(p - M);
        m = M;
    }
    #pragma unroll
    for (int o = 16; o > 0; o >>= 1) {
        float m2 = __shfl_xor_sync(0xffffffffu, m, o);
        float s2 = __shfl_xor_sync(0xffffffffu, s, o);
        merge_ms(m, s, m2, s2);
    }
    __syncthreads();
    if (lid == 0) { sh_m[wid] = m; sh_s[wid] = s; }
    __syncthreads();
    if (wid == 0) {
        float pm = (lid < WPB) ? sh_m[lid] : -1e30f;
        float ps = (lid < WPB) ? sh_s[lid] : 0.f;
        #pragma unroll
        for (int o = 16; o > 0; o >>= 1) {
            float m2 = __shfl_xor_sync(0xffffffffu, pm, o);
            float s2 = __shfl_xor_sync(0xffffffffu, ps, o);
            merge_ms(pm, ps, m2, s2);
        }
        if (lid == 0) { g_m_part[bid] = pm; g_s_part[bid] = ps; }
    }

    // arrive the replay-guard barrier (covers slot reset + softmax partials)
    unsigned bar_target = 0u;
    if (tid == 0) {
        __threadfence();
        unsigned tk = atomicAdd(&g_bar, 1u) + 1u;
        bar_target = ((tk + (unsigned)nb - 1u) / (unsigned)nb) * (unsigned)nb;
    }

    // ---------------- A2: normalize -> per-row-scaled int8 into REGISTERS ----------------
    uint4 a[RPW];
    const bool  mine  = (lid < RPW) && (rbase + lid < NITEMS);
    const int   myrow = rbase + lid;
    float my_inva = 0.f, mypred = -1e30f;
    if (mine) mypred = pred[myrow];

    {
        const float4* Erow = reinterpret_cast<const float4*>(E) + (size_t)rbase * (DIM / 4);
        float4 cur[4];
        if (rbase < NITEMS) {
            #pragma unroll
            for (int j = 0; j < 4; j++) cur[j] = Erow[j * 32 + lid];
        }
        #pragma unroll
        for (int i = 0; i < RPW; i++) {
            int row = rbase + i;
            float4 nxt[4];
            bool have_n = (i + 1 < RPW) && (row + 1 < NITEMS);
            if (have_n) {
                const float4* Er2 = Erow + (size_t)(i + 1) * (DIM / 4);
                #pragma unroll
                for (int j = 0; j < 4; j++) nxt[j] = Er2[j * 32 + lid];
            }
            if (row < NITEMS) {
                float ss2 = 0.f;
                #pragma unroll
                for (int j = 0; j < 4; j++)
                    ss2 += cur[j].x * cur[j].x + cur[j].y * cur[j].y
                         + cur[j].z * cur[j].z + cur[j].w * cur[j].w;
                ss2 = warp_sum_xor(ss2);
                const float inv = 1.0f / (sqrtf(ss2) + 1e-12f);
                float xv[16];
                #pragma unroll
                for (int j = 0; j < 4; j++) {
                    xv[j * 4 + 0] = cur[j].x * inv;
                    xv[j * 4 + 1] = cur[j].y * inv;
                    xv[j * 4 + 2] = cur[j].z * inv;
                    xv[j * 4 + 3] = cur[j].w * inv;
                }
                float am = 0.f;
                #pragma unroll
                for (int q = 0; q < 16; q++) am = fmaxf(am, fabsf(xv[q]));
                unsigned amu = __reduce_max_sync(0xffffffffu, __float_as_uint(am));
                float xmax = __uint_as_float(amu);
                float scale = 127.0f / xmax;
                float inva  = xmax * (1.0f / 127.0f);
                int q[16];
                #pragma unroll
                for (int t2 = 0; t2 < 16; t2++) q[t2] = __float2int_rn(xv[t2] * scale);
                a[i].x = pack4_s8(q[0],  q[1],  q[2],  q[3]);
                a[i].y = pack4_s8(q[4],  q[5],  q[6],  q[7]);
                a[i].z = pack4_s8(q[8],  q[9],  q[10], q[11]);
                a[i].w = pack4_s8(q[12], q[13], q[14], q[15]);
                if (lid == i) my_inva = inva;
            } else {
                a[i] = make_uint4(0u, 0u, 0u, 0u);
            }
            #pragma unroll
            for (int j = 0; j < 4; j++) cur[j] = nxt[j];
        }
    }

    // ---------- t=0: argmax(pred) (== argmax(rel), softmax monotone) ----------
    {
        unsigned e = mine ? flip_f(mypred) : 0u;
        unsigned mx = __reduce_max_sync(0xffffffffu, e);
        unsigned ball = __ballot_sync(0xffffffffu, e == mx);
        int src = __ffs(ball) - 1;                       // lane == local row (lowest-row tie-break)
        int wrow = __shfl_sync(0xffffffffu, myrow, src);
        uint4 csel = a[0];
        #pragma unroll
        for (int r = 1; r < RPW; r++) if (src == r) csel = a[r];
        float winva = __shfl_sync(0xffffffffu, my_inva, src);
        if (mx != 0u) {
            g_wcand[0][gw][lid] = csel;                  // speculative per-warp candidate
            if (lid == 0) g_winfo[0][gw] = make_float2(0.f, winva);  // rel filled later path
        }
        if (lid == 0) { sh_e[wid] = mx; sh_r[wid] = wrow; }
    }
    __syncthreads();
    if (wid == 0) {
        unsigned e2 = (lid < WPB) ? sh_e[lid] : 0u;
        int      r2 = (lid < WPB) ? sh_r[lid] : 0;
        unsigned mx2 = __reduce_max_sync(0xffffffffu, e2);
        unsigned b2  = __ballot_sync(0xffffffffu, e2 == mx2);
        int src2 = __ffs(b2) - 1;
        int row2 = __shfl_sync(0xffffffffu, r2, src2);
        if (lid == 0) {
            // replay guard: all blocks arrived long ago (during A2) -> ~free
            while (*((volatile unsigned*)&g_bar) < bar_target) { }
            if (mx2 != 0u) {
                unsigned long long bb = ((unsigned long long)mx2 << 32) | (unsigned)(~row2);
                atomicMax(&g_slot[0].best, bb);
            }
            __threadfence();                             // release: cand STGs (bar-ordered) + max
            atomicAdd(&g_slot[0].cnt, 1u);
        }
        unsigned long long w = slot_wait(&g_slot[0], (unsigned)nb);
        __threadfence();                                 // acquire
        // merge softmax partials (published before each block's slot0 arrive)
        float pm = -1e30f, ps = 0.f;
        for (int j = lid; j < nb; j += 32)
            merge_ms(pm, ps, __ldcg(&g_m_part[j]), __ldcg(&g_s_part[j]));
        #pragma unroll
        for (int o = 16; o > 0; o >>= 1) {
            float m2 = __shfl_xor_sync(0xffffffffu, pm, o);
            float s2 = __shfl_xor_sync(0xffffffffu, ps, o);
            merge_ms(pm, ps, m2, s2);
        }
        const int idx0 = (int)(~(unsigned int)w);
        const int gs   = idx0 / RPW;
        sh_v4[lid] = __ldcg(&g_wcand[0][gs][lid]);
        if (lid == 0) {
            sh_bm = pm; sh_bs = ps;
            sh_vinv = __ldcg(&g_winfo[0][gs]).y;
            sh_widx = idx0;
        }
    }
    __syncthreads();
    const float pmax = sh_bm;
    const float invS = 1.0f / sh_bs;
    float myrel = mine ? expf(mypred - pmax) * invS : 0.f;
    float myms  = 0.f;

    // err accumulation on warp1 lane0 (tid 32); err0 from pred directly
    float err_acc = 0.f, decay_t = 1.0f;
    if (bid == 0 && tid == 32)
        err_acc = expf(__ldcg(&pred[sh_widx]) - pmax) * invS;

    // ---------------- greedy loop: 15 passes, all-register GEMV ----------------
    for (int t = 0; t < KSEL - 1; t++) {
        const int   idx  = sh_widx;
        const float vinv = sh_vinv;
        const uint4 vv   = sh_v4[lid];

        float mysim = 0.f;
        #pragma unroll
        for (int i = 0; i < RPW; i++) {
            int d = __dp4a((int)a[i].x, (int)vv.x, 0);
            d = __dp4a((int)a[i].y, (int)vv.y, d);
            d = __dp4a((int)a[i].z, (int)vv.z, d);
            d = __dp4a((int)a[i].w, (int)vv.w, d);
            int ss = (int)__reduce_add_sync(0xffffffffu, (unsigned)d);
            if (lid == i) mysim = (float)ss;
        }
        mysim *= my_inva * vinv;

        const float decay_next = decay_t * DECAYF;
        unsigned e = 0u;
        if (mine) {
            myms = (myrow == idx) ? 1e30f : fmaxf(myms, mysim);
            e = flip_f(decay_next * myrel - LAMBDA * myms);
        }
        unsigned mx = __reduce_max_sync(0xffffffffu, e);
        unsigned ball = __ballot_sync(0xffffffffu, e == mx);
        int src = __ffs(ball) - 1;
        int wrow = __shfl_sync(0xffffffffu, myrow, src);
        uint4 csel = a[0];
        #pragma unroll
        for (int r = 1; r < RPW; r++) if (src == r) csel = a[r];
        float wrel  = __shfl_sync(0xffffffffu, myrel, src);
        float winva = __shfl_sync(0xffffffffu, my_inva, src);
        const int buf = (t + 1) & 1;
        const int k   = t + 1;
        if (mx != 0u) {
            g_wcand[buf][gw][lid] = csel;               // speculative publish before barrier
            if (lid == 0) g_winfo[buf][gw] = make_float2(wrel, winva);
        }
        if (lid == 0) { sh_e[wid] = mx; sh_r[wid] = wrow; }
        __syncthreads();                                 // #1 (orders all warps' STGs before fence)

        if (wid == 0) {
            unsigned e2 = (lid < WPB) ? sh_e[lid] : 0u;
            int      r2 = (lid < WPB) ? sh_r[lid] : 0;
            unsigned mx2 = __reduce_max_sync(0xffffffffu, e2);
            unsigned b2  = __ballot_sync(0xffffffffu, e2 == mx2);
            int src2 = __ffs(b2) - 1;
            int row2 = __shfl_sync(0xffffffffu, r2, src2);
            if (lid == 0) {
                if (mx2 != 0u) {
                    unsigned long long bb = ((unsigned long long)mx2 << 32) | (unsigned)(~row2);
                    atomicMax(&g_slot[k].best, bb);
                }
                __threadfence();
                atomicAdd(&g_slot[k].cnt, 1u);
            }
            unsigned long long w = slot_wait(&g_slot[k], (unsigned)nb);
            __threadfence();
            const int nidx = (int)(~(unsigned int)w);
            const int gs   = nidx / RPW;
            if (k < KSEL - 1) {                          // last winner needs no vector
                sh_v4[lid] = __ldcg(&g_wcand[buf][gs][lid]);
                if (lid == 0) sh_vinv = __ldcg(&g_winfo[buf][gs]).y;
            }
            if (lid == 0) sh_widx = nidx;
        }
        __syncthreads();                                 // #2

        decay_t = decay_next;
        if (bid == 0 && tid == 32)
            err_acc += __ldcg(&g_winfo[buf][sh_widx / RPW]).x * decay_t;
    }

    // mmr_loss = -sum over selected of max_j cos = -sum of diagonal = -KSEL (fp32-exact)
    if (bid == 0 && tid == 32)
        out[0] = -err_acc - LAMBDA * (float)KSEL;
}

extern "C" void kernel_launch(void* const* d_in, const int* in_sizes, int n_in,
                              void* d_out, int out_size) {
    (void)in_sizes; (void)n_in; (void)out_size;
    const float* pred = (const float*)d_in[0];
    const float* E    = (const float*)d_in[5];   // explanation_embeddings [32768, 512]
    float* out        = (float*)d_out;

    int dev = 0;
    cudaGetDevice(&dev);
    int nsm = 0;
    cudaDeviceGetAttribute(&nsm, cudaDevAttrMultiProcessorCount, dev);
    if (nsm <= 0) nsm = 148;
    if (nsm > MAXB) nsm = MAXB;

    ranking_kernel<<<nsm, NTHREADS>>>(pred, E, out, nsm);
}